// round 1
// baseline (speedup 1.0000x reference)
#include <cuda_runtime.h>
#include <math.h>

#define BB 4
#define TT 1024
#define DD 1024
#define HH 16
#define DHH 64
#define DFF 4096
#define RR 8
#define BT (BB*TT)          // 4096
#define BTD (BB*TT*DD)      // 4194304

// ---------------- device scratch ----------------
__device__ float g_cur[BTD];
__device__ float g_norm[BTD];
__device__ float g_q[BTD];
__device__ float g_k[BTD];
__device__ float g_v[BTD];
__device__ float g_o[BTD];
__device__ float g_xo[BTD];
__device__ float g_attn[(size_t)BB*HH*TT*TT];   // 67,108,864 floats
__device__ float g_mid[BB*TT*DFF];              // 16,777,216 floats
__device__ float g_part[BB*32*DD];
__device__ float g_ctxm[BB*DD];
__device__ float g_ctx[BB*DD];
__device__ float g_h1[BB*256];
__device__ float g_gate[BB];
__device__ float g_gm;
__device__ int   g_idx[3];

__device__ __forceinline__ float geluf(float x){
    return 0.5f*x*(1.0f+erff(x*0.7071067811865476f));
}

// ---------------- utility kernels ----------------
__global__ void k_copy4(const float4* __restrict__ in, float4* __restrict__ out){
    int i = blockIdx.x*256 + threadIdx.x;
    out[i] = in[i];
}
__global__ void k_copy_in(const float* __restrict__ x){
    int i = blockIdx.x*256 + threadIdx.x;
    ((float4*)g_cur)[i] = ((const float4*)x)[i];
}
__global__ void k_copy_out(float* __restrict__ out){
    int i = blockIdx.x*256 + threadIdx.x;
    ((float4*)out)[i] = ((const float4*)g_cur)[i];
}
__global__ void k_mix(){
    int i = blockIdx.x*256 + threadIdx.x;
    float gm = g_gm;
    float4 c = ((const float4*)g_cur)[i];
    float4 xo = ((const float4*)g_xo)[i];
    c.x += gm*(xo.x-c.x); c.y += gm*(xo.y-c.y);
    c.z += gm*(xo.z-c.z); c.w += gm*(xo.w-c.w);
    ((float4*)g_cur)[i] = c;
}

// mean over T: two stage
__global__ void k_meanT_part(const float* __restrict__ in){
    int b = blockIdx.x, c = blockIdx.y;           // c in [0,32)
    int t0 = c*32;
    for(int d = threadIdx.x; d < DD; d += 256){
        float s = 0.f;
        for(int t = t0; t < t0+32; t++) s += in[((size_t)(b*TT+t))*DD + d];
        g_part[(size_t)(b*32+c)*DD + d] = s;
    }
}
__global__ void k_meanT_reduce(){
    int b = blockIdx.x;
    for(int d = threadIdx.x; d < DD; d += 256){
        float s = 0.f;
        for(int c = 0; c < 32; c++) s += g_part[(size_t)(b*32+c)*DD + d];
        g_ctxm[b*DD + d] = s*(1.0f/TT);
    }
}

// ctx = ctxm @ ctx_w + ctx_b  (4 x 1024)
__global__ void k_ctx(const float* __restrict__ W, const float* __restrict__ bias){
    int b = blockIdx.x;
    int n = blockIdx.y*256 + threadIdx.x;
    const float* xv = &g_ctxm[b*DD];
    float s = bias[n];
    for(int k = 0; k < DD; k++) s += xv[k]*W[(size_t)k*DD + n];
    g_ctx[b*DD + n] = s;
}

// router: warp/adj/direct/gate_scores + top-3
__global__ void k_router(const float* __restrict__ summaries, const float* __restrict__ base_adj,
                         const float* __restrict__ warp_w, const float* __restrict__ warp_b,
                         const float* __restrict__ gate_w, const float* __restrict__ gate_b,
                         float* __restrict__ out_gs, float* __restrict__ out_adj,
                         float* __restrict__ out_mh){
    __shared__ float s_warp[BB][64];
    __shared__ float s_dir[BB][RR];
    __shared__ float s_gl[BB][RR];
    __shared__ float s_gs[BB][RR];
    int tid = threadIdx.x;
    {   int b = tid/64, c = tid%64;
        const float* xv = &g_ctx[b*DD];
        float s = warp_b[c];
        for(int k = 0; k < DD; k++) s += xv[k]*warp_w[(size_t)k*64 + c];
        s_warp[b][c] = s*0.1f;
    }
    if(tid < 32){
        int b = tid/8, r = tid%8;
        const float* xv = &g_ctx[b*DD];
        float s = 0.f;
        for(int k = 0; k < DD; k++) s += xv[k]*summaries[r*DD + k];
        s_dir[b][r] = s;
    } else if(tid < 64){
        int t = tid-32; int b = t/8, r = t%8;
        const float* xv = &g_ctx[b*DD];
        float s = gate_b[r];
        for(int k = 0; k < DD; k++) s += xv[k]*gate_w[k*RR + r];
        s_gl[b][r] = s;
    }
    __syncthreads();
    if(tid < 32){
        int b = tid/8, i = tid%8;
        float v[8]; float mx = -1e30f;
        for(int j = 0; j < 8; j++){ v[j] = base_adj[i*8+j] + s_warp[b][i*8+j]; mx = fmaxf(mx, v[j]); }
        float sum = 0.f;
        for(int j = 0; j < 8; j++){ v[j] = expf(v[j]-mx); sum += v[j]; }
        float inv = 1.0f/sum;
        float boost = 0.f;
        for(int j = 0; j < 8; j++){
            float a = v[j]*inv;
            out_adj[(b*8+i)*8 + j] = a;
            boost += a*s_dir[b][j];
        }
        float gs = 1.0f/(1.0f+expf(-(s_gl[b][i]+boost)*0.5f));
        out_gs[b*8+i] = gs;
        s_gs[b][i] = gs;
    }
    __syncthreads();
    if(tid == 0){
        float m[RR];
        for(int r = 0; r < 8; r++) m[r] = 0.25f*(s_gs[0][r]+s_gs[1][r]+s_gs[2][r]+s_gs[3][r]);
        for(int h = 0; h < 3; h++){
            int best = 0; float bv = -1e30f;
            for(int r = 0; r < 8; r++) if(m[r] > bv){ bv = m[r]; best = r; }
            g_idx[h] = best; m[best] = -1e30f;
        }
        out_mh[0] = 3.0f;
    }
}

// gate MLP stage 1: h1 = gelu(ctxm @ g1_w[room] + g1_b[room])  (B x 256)
__global__ void k_g1(const float* __restrict__ g1_w, const float* __restrict__ g1_b, int hop){
    int room = g_idx[hop];
    int b = blockIdx.x, n = threadIdx.x;   // 256 threads
    const float* W = g1_w + (size_t)room*DD*256;
    const float* xv = &g_ctxm[b*DD];
    float s = g1_b[room*256 + n];
    for(int k = 0; k < DD; k++) s += xv[k]*W[(size_t)k*256 + n];
    g_h1[b*256 + n] = geluf(s);
}
// gate MLP stage 2 + gm
__global__ void k_g2(const float* __restrict__ g2_w, const float* __restrict__ g2_b, int hop){
    int room = g_idx[hop];
    __shared__ float red[256];
    int tid = threadIdx.x;
    int b = tid/64, lane = tid%64;
    const float* W = g2_w + room*256;
    float s = 0.f;
    for(int k = lane; k < 256; k += 64) s += g_h1[b*256 + k]*W[k];
    red[tid] = s; __syncthreads();
    for(int off = 32; off >= 1; off >>= 1){
        if(lane < off) red[tid] += red[tid+off];
        __syncthreads();
    }
    if(lane == 0){
        float gate = 1.0f/(1.0f+expf(-(red[tid]+g2_b[room])));
        g_gate[b] = gate;
    }
    __syncthreads();
    if(tid == 0) g_gm = 0.25f*(g_gate[0]+g_gate[1]+g_gate[2]+g_gate[3]);
}

// layernorm (optionally pre-scaled by gate[b]); per-room gamma/beta if hop>=0
__global__ void __launch_bounds__(256) k_ln(const float* __restrict__ in,
                     const float* __restrict__ gb, const float* __restrict__ bb,
                     int hop, const float* __restrict__ gate, float* __restrict__ out){
    int row = blockIdx.x; int b = row >> 10;
    int room = (hop >= 0) ? g_idx[hop] : 0;
    float sc = gate ? gate[b] : 1.0f;
    float4 v = ((const float4*)(in + (size_t)row*DD))[threadIdx.x];
    v.x *= sc; v.y *= sc; v.z *= sc; v.w *= sc;
    __shared__ float rs[256], rq[256];
    rs[threadIdx.x] = v.x+v.y+v.z+v.w;
    rq[threadIdx.x] = v.x*v.x+v.y*v.y+v.z*v.z+v.w*v.w;
    __syncthreads();
    for(int off = 128; off >= 1; off >>= 1){
        if(threadIdx.x < off){ rs[threadIdx.x] += rs[threadIdx.x+off]; rq[threadIdx.x] += rq[threadIdx.x+off]; }
        __syncthreads();
    }
    float mean = rs[0]*(1.0f/DD);
    float var  = rq[0]*(1.0f/DD) - mean*mean;
    float inv  = rsqrtf(var + 1e-5f);
    float4 g4 = ((const float4*)(gb + (size_t)room*DD))[threadIdx.x];
    float4 b4 = ((const float4*)(bb + (size_t)room*DD))[threadIdx.x];
    float4 o4;
    o4.x = (v.x-mean)*inv*g4.x + b4.x;
    o4.y = (v.y-mean)*inv*g4.y + b4.y;
    o4.z = (v.z-mean)*inv*g4.z + b4.z;
    o4.w = (v.w-mean)*inv*g4.w + b4.w;
    ((float4*)(out + (size_t)row*DD))[threadIdx.x] = o4;
}

// generic SGEMM: C[M,N] = A[M,K] @ W[K,N] + bias, opt gelu, opt residual (with per-batch scale)
// 64x64 tile, BK=16, 256 threads, 4x4 micro. M assumed multiple of 64 (here 4096).
__global__ void __launch_bounds__(256) k_gemm(const float* __restrict__ A,
        const float* __restrict__ Wb, const float* __restrict__ bbase,
        const float* __restrict__ res, const float* __restrict__ rscale,
        float* __restrict__ C, int N, int K, int hop,
        long wstr, long bstr, int act){
    int room = (hop >= 0) ? g_idx[hop] : 0;
    const float* W    = Wb    + (size_t)room*wstr;
    const float* bias = bbase + (size_t)room*bstr;
    __shared__ float As[16][64];
    __shared__ float Bs[16][64];
    int tid = threadIdx.x;
    int bm = blockIdx.y, bn = blockIdx.x;
    int tx = tid%16, ty = tid/16;
    int ar = tid>>2, ac = (tid&3)*4;
    const float* Aptr = A + (size_t)(bm*64+ar)*K + ac;
    const float* Wptr = W + (size_t)ty*N + bn*64 + tx*4;
    float acc[4][4] = {};
    for(int k0 = 0; k0 < K; k0 += 16){
        float4 av = *(const float4*)(Aptr + k0);
        As[ac+0][ar] = av.x; As[ac+1][ar] = av.y; As[ac+2][ar] = av.z; As[ac+3][ar] = av.w;
        float4 bv = *(const float4*)(Wptr + (size_t)k0*N);
        *(float4*)&Bs[ty][tx*4] = bv;
        __syncthreads();
        #pragma unroll
        for(int kk = 0; kk < 16; kk++){
            float4 ra = *(const float4*)&As[kk][ty*4];
            float4 rb = *(const float4*)&Bs[kk][tx*4];
            acc[0][0] += ra.x*rb.x; acc[0][1] += ra.x*rb.y; acc[0][2] += ra.x*rb.z; acc[0][3] += ra.x*rb.w;
            acc[1][0] += ra.y*rb.x; acc[1][1] += ra.y*rb.y; acc[1][2] += ra.y*rb.z; acc[1][3] += ra.y*rb.w;
            acc[2][0] += ra.z*rb.x; acc[2][1] += ra.z*rb.y; acc[2][2] += ra.z*rb.z; acc[2][3] += ra.z*rb.w;
            acc[3][0] += ra.w*rb.x; acc[3][1] += ra.w*rb.y; acc[3][2] += ra.w*rb.z; acc[3][3] += ra.w*rb.w;
        }
        __syncthreads();
    }
    int m0 = bm*64 + ty*4, n0 = bn*64 + tx*4;
    float4 bi = *(const float4*)&bias[n0];
    #pragma unroll
    for(int i = 0; i < 4; i++){
        int m = m0 + i;
        float vx[4] = { acc[i][0]+bi.x, acc[i][1]+bi.y, acc[i][2]+bi.z, acc[i][3]+bi.w };
        if(act == 1){
            vx[0] = geluf(vx[0]); vx[1] = geluf(vx[1]); vx[2] = geluf(vx[2]); vx[3] = geluf(vx[3]);
        }
        if(res){
            float sc = rscale ? rscale[m>>10] : 1.0f;
            float4 rv = *(const float4*)&res[(size_t)m*N + n0];
            vx[0] += rv.x*sc; vx[1] += rv.y*sc; vx[2] += rv.z*sc; vx[3] += rv.w*sc;
        }
        float4 ov = { vx[0], vx[1], vx[2], vx[3] };
        *(float4*)&C[(size_t)m*N + n0] = ov;
    }
}

// attention scores: s[bh, i, j] = q_i . k_j / 8, only lower tiles computed
__global__ void __launch_bounds__(256) k_scores(const float* __restrict__ q, const float* __restrict__ kx){
    int ti = blockIdx.x, tj = blockIdx.y;
    if(tj > ti) return;
    int bh = blockIdx.z; int b = bh/HH, h = bh%HH;
    __shared__ float qs[64][64];   // [k][m]
    __shared__ float ks[64][64];   // [k][n]
    int tid = threadIdx.x;
    int r = tid>>2, c0 = (tid&3)*16;
    const float* qp = q  + (size_t)(b*TT + ti*64 + r)*DD + h*64;
    const float* kp = kx + (size_t)(b*TT + tj*64 + r)*DD + h*64;
    #pragma unroll
    for(int it = 0; it < 4; it++){
        int c = c0 + it*4;
        float4 v = *(const float4*)(qp + c);
        qs[c+0][r] = v.x; qs[c+1][r] = v.y; qs[c+2][r] = v.z; qs[c+3][r] = v.w;
        float4 w = *(const float4*)(kp + c);
        ks[c+0][r] = w.x; ks[c+1][r] = w.y; ks[c+2][r] = w.z; ks[c+3][r] = w.w;
    }
    __syncthreads();
    int tx = tid%16, ty = tid/16;
    float acc[4][4] = {};
    #pragma unroll 4
    for(int k2 = 0; k2 < 64; k2++){
        float4 ra = *(const float4*)&qs[k2][ty*4];
        float4 rb = *(const float4*)&ks[k2][tx*4];
        acc[0][0] += ra.x*rb.x; acc[0][1] += ra.x*rb.y; acc[0][2] += ra.x*rb.z; acc[0][3] += ra.x*rb.w;
        acc[1][0] += ra.y*rb.x; acc[1][1] += ra.y*rb.y; acc[1][2] += ra.y*rb.z; acc[1][3] += ra.y*rb.w;
        acc[2][0] += ra.z*rb.x; acc[2][1] += ra.z*rb.y; acc[2][2] += ra.z*rb.z; acc[2][3] += ra.z*rb.w;
        acc[3][0] += ra.w*rb.x; acc[3][1] += ra.w*rb.y; acc[3][2] += ra.w*rb.z; acc[3][3] += ra.w*rb.w;
    }
    #pragma unroll
    for(int i = 0; i < 4; i++){
        int ii = ti*64 + ty*4 + i;
        float* sp = g_attn + ((size_t)bh*TT + ii)*TT + tj*64 + tx*4;
        float4 ov = { acc[i][0]*0.125f, acc[i][1]*0.125f, acc[i][2]*0.125f, acc[i][3]*0.125f };
        *(float4*)sp = ov;
    }
}

// row softmax with causal truncation + zero fill
__global__ void __launch_bounds__(128) k_softmax(){
    int row = blockIdx.x;              // bh*T + i
    int i = row & (TT-1);
    float* p = g_attn + (size_t)row*TT;
    int len = i+1, tid = threadIdx.x;
    __shared__ float red[128];
    float mx = -1e30f;
    for(int j = tid; j < len; j += 128) mx = fmaxf(mx, p[j]);
    red[tid] = mx; __syncthreads();
    for(int off = 64; off >= 1; off >>= 1){
        if(tid < off) red[tid] = fmaxf(red[tid], red[tid+off]);
        __syncthreads();
    }
    mx = red[0]; __syncthreads();
    float s = 0.f;
    for(int j = tid; j < len; j += 128){ float e = expf(p[j]-mx); p[j] = e; s += e; }
    red[tid] = s; __syncthreads();
    for(int off = 64; off >= 1; off >>= 1){
        if(tid < off) red[tid] += red[tid+off];
        __syncthreads();
    }
    float inv = 1.0f/red[0];
    for(int j = tid; j < len; j += 128) p[j] *= inv;
    for(int j = len + tid; j < TT; j += 128) p[j] = 0.f;
}

// o = a @ v per (bh), causal K-truncation
__global__ void __launch_bounds__(256) k_av(const float* __restrict__ v, float* __restrict__ o){
    int ti = blockIdx.x; int bh = blockIdx.y;
    int b = bh/HH, h = bh%HH;
    __shared__ float as[64][64];   // [k][m]
    __shared__ float vs[64][64];   // [k][n]
    int tid = threadIdx.x;
    int r = tid>>2, c0 = (tid&3)*16;
    int tx = tid%16, ty = tid/16;
    float acc[4][4] = {};
    for(int kt = 0; kt <= ti; kt++){
        const float* ap = g_attn + ((size_t)bh*TT + ti*64 + r)*TT + kt*64;
        const float* vp = v + (size_t)(b*TT + kt*64 + r)*DD + h*64;
        #pragma unroll
        for(int it = 0; it < 4; it++){
            int c = c0 + it*4;
            float4 va = *(const float4*)(ap + c);
            as[c+0][r] = va.x; as[c+1][r] = va.y; as[c+2][r] = va.z; as[c+3][r] = va.w;
            float4 vv = *(const float4*)(vp + c);
            *(float4*)&vs[r][c] = vv;   // vs[k][n] with k=r rows? -- careful below
        }
        __syncthreads();
        #pragma unroll 4
        for(int k2 = 0; k2 < 64; k2++){
            float4 ra = *(const float4*)&as[k2][ty*4];
            float4 rb = *(const float4*)&vs[k2][tx*4];
            acc[0][0] += ra.x*rb.x; acc[0][1] += ra.x*rb.y; acc[0][2] += ra.x*rb.z; acc[0][3] += ra.x*rb.w;
            acc[1][0] += ra.y*rb.x; acc[1][1] += ra.y*rb.y; acc[1][2] += ra.y*rb.z; acc[1][3] += ra.y*rb.w;
            acc[2][0] += ra.z*rb.x; acc[2][1] += ra.z*rb.y; acc[2][2] += ra.z*rb.z; acc[2][3] += ra.z*rb.w;
            acc[3][0] += ra.w*rb.x; acc[3][1] += ra.w*rb.y; acc[3][2] += ra.w*rb.z; acc[3][3] += ra.w*rb.w;
        }
        __syncthreads();
    }
    #pragma unroll
    for(int i = 0; i < 4; i++){
        int ii = ti*64 + ty*4 + i;
        float* op = o + (size_t)(b*TT + ii)*DD + h*64 + tx*4;
        float4 ov = { acc[i][0], acc[i][1], acc[i][2], acc[i][3] };
        *(float4*)op = ov;
    }
}

// NOTE on k_av vs layout: as[][] is stored transposed ([j][m]); vs[][] is stored
// row-major where vs[j][n] holds v[key j][dim n] because the load row index r
// IS the key index within the tile. Both feed the same k2-major inner loop.

extern "C" void kernel_launch(void* const* d_in, const int* in_sizes, int n_in,
                              void* d_out, int out_size){
    const float* x         = (const float*)d_in[0];
    const float* summaries = (const float*)d_in[1];
    const float* ctx_w     = (const float*)d_in[2];
    const float* ctx_b     = (const float*)d_in[3];
    const float* base_adj  = (const float*)d_in[4];
    const float* warp_w    = (const float*)d_in[5];
    const float* warp_b    = (const float*)d_in[6];
    const float* gate_w    = (const float*)d_in[7];
    const float* gate_b    = (const float*)d_in[8];
    const float* g1_w      = (const float*)d_in[9];
    const float* g1_b      = (const float*)d_in[10];
    const float* g2_w      = (const float*)d_in[11];
    const float* g2_b      = (const float*)d_in[12];
    const float* ln1_g     = (const float*)d_in[13];
    const float* ln1_b     = (const float*)d_in[14];
    const float* wq        = (const float*)d_in[15];
    const float* bq        = (const float*)d_in[16];
    const float* wk        = (const float*)d_in[17];
    const float* bk        = (const float*)d_in[18];
    const float* wv        = (const float*)d_in[19];
    const float* bv        = (const float*)d_in[20];
    const float* wo        = (const float*)d_in[21];
    const float* bo        = (const float*)d_in[22];
    const float* ln2_g     = (const float*)d_in[23];
    const float* ln2_b     = (const float*)d_in[24];
    const float* ff1_w     = (const float*)d_in[25];
    const float* ff1_b     = (const float*)d_in[26];
    const float* ff2_w     = (const float*)d_in[27];
    const float* ff2_b     = (const float*)d_in[28];
    float* out = (float*)d_out;

    float *p_cur, *p_norm, *p_q, *p_k, *p_v, *p_o, *p_xo, *p_mid, *p_gate;
    cudaGetSymbolAddress((void**)&p_cur,  g_cur);
    cudaGetSymbolAddress((void**)&p_norm, g_norm);
    cudaGetSymbolAddress((void**)&p_q,    g_q);
    cudaGetSymbolAddress((void**)&p_k,    g_k);
    cudaGetSymbolAddress((void**)&p_v,    g_v);
    cudaGetSymbolAddress((void**)&p_o,    g_o);
    cudaGetSymbolAddress((void**)&p_xo,   g_xo);
    cudaGetSymbolAddress((void**)&p_mid,  g_mid);
    cudaGetSymbolAddress((void**)&p_gate, g_gate);

    const int CP_BLKS = BTD/4/256;

    // init working buffer
    k_copy_in<<<CP_BLKS,256>>>(x);

    // ---- router ----
    k_meanT_part<<<dim3(BB,32),256>>>(x);
    k_meanT_reduce<<<BB,256>>>();
    k_ctx<<<dim3(BB,4),256>>>(ctx_w, ctx_b);
    k_router<<<1,256>>>(summaries, base_adj, warp_w, warp_b, gate_w, gate_b,
                        out + BTD, out + BTD + 32, out + BTD + 32 + 256);

    // ---- 3 hops ----
    for(int hop = 0; hop < 3; hop++){
        k_meanT_part<<<dim3(BB,32),256>>>(p_cur);
        k_meanT_reduce<<<BB,256>>>();
        k_g1<<<BB,256>>>(g1_w, g1_b, hop);
        k_g2<<<1,256>>>(g2_w, g2_b, hop);
        // ln1(xg)
        k_ln<<<BT,256>>>(p_cur, ln1_g, ln1_b, hop, p_gate, p_norm);
        // q,k,v
        k_gemm<<<dim3(16,64),256>>>(p_norm, wq, bq, nullptr, nullptr, p_q, DD, DD, hop, (long)DD*DD, DD, 0);
        k_gemm<<<dim3(16,64),256>>>(p_norm, wk, bk, nullptr, nullptr, p_k, DD, DD, hop, (long)DD*DD, DD, 0);
        k_gemm<<<dim3(16,64),256>>>(p_norm, wv, bv, nullptr, nullptr, p_v, DD, DD, hop, (long)DD*DD, DD, 0);
        // attention
        k_scores<<<dim3(16,16,BB*HH),256>>>(p_q, p_k);
        k_softmax<<<BB*HH*TT,128>>>();
        k_av<<<dim3(16,BB*HH),256>>>(p_v, p_o);
        // xo = xg + o@wo + bo   (xg = cur*gate)
        k_gemm<<<dim3(16,64),256>>>(p_o, wo, bo, p_cur, p_gate, p_xo, DD, DD, hop, (long)DD*DD, DD, 0);
        // ffn
        k_ln<<<BT,256>>>(p_xo, ln2_g, ln2_b, hop, nullptr, p_norm);
        k_gemm<<<dim3(64,64),256>>>(p_norm, ff1_w, ff1_b, nullptr, nullptr, p_mid, DFF, DD, hop, (long)DD*DFF, DFF, 1);
        k_gemm<<<dim3(16,64),256>>>(p_mid, ff2_w, ff2_b, p_xo, nullptr, p_xo, DD, DFF, hop, (long)DFF*DD, DD, 0);
        // cur = cur + gm*(xo - cur)
        k_mix<<<CP_BLKS,256>>>();
    }

    k_copy_out<<<CP_BLKS,256>>>(out);
}

// round 2
// speedup vs baseline: 1.5008x; 1.5008x over previous
#include <cuda_runtime.h>
#include <math.h>
#include <stdint.h>

#define BB 4
#define TT 1024
#define DD 1024
#define HH 16
#define DHH 64
#define DFF 4096
#define RR 8
#define BT (BB*TT)          // 4096
#define BTD (BB*TT*DD)      // 4194304

// ---------------- device scratch ----------------
__device__ float g_cur[BTD];
__device__ float g_norm[BTD];
__device__ float g_q[BTD];
__device__ float g_k[BTD];
__device__ float g_v[BTD];
__device__ float g_o[BTD];
__device__ float g_xo[BTD];
__device__ float g_attn[(size_t)BB*HH*TT*TT];   // 67,108,864 floats
__device__ float g_mid[BB*TT*DFF];              // 16,777,216 floats
__device__ float g_part[BB*32*DD];
__device__ float g_ctxm[BB*DD];
__device__ float g_ctx[BB*DD];
__device__ float g_h1[BB*256];
__device__ float g_gate[BB];
__device__ float g_gm;
__device__ int   g_idx[3];

__device__ __forceinline__ float geluf(float x){
    return 0.5f*x*(1.0f+erff(x*0.7071067811865476f));
}

// ---------------- tf32 mma helpers ----------------
__device__ __forceinline__ uint32_t f2tf(float f){
    uint32_t u; asm("cvt.rna.tf32.f32 %0, %1;" : "=r"(u) : "f"(f)); return u;
}
__device__ __forceinline__ void split_tf(float f, uint32_t &hi, uint32_t &lo){
    hi = f2tf(f);
    lo = f2tf(f - __uint_as_float(hi));
}
__device__ __forceinline__ void mma_tf32(float* c, uint32_t a0, uint32_t a1, uint32_t a2, uint32_t a3,
                                         uint32_t b0, uint32_t b1){
    asm volatile("mma.sync.aligned.m16n8k8.row.col.f32.tf32.tf32.f32 "
        "{%0,%1,%2,%3},{%4,%5,%6,%7},{%8,%9},{%0,%1,%2,%3};"
        : "+f"(c[0]), "+f"(c[1]), "+f"(c[2]), "+f"(c[3])
        : "r"(a0), "r"(a1), "r"(a2), "r"(a3), "r"(b0), "r"(b1));
}

// ---------------- utility kernels ----------------
__global__ void k_copy_in(const float* __restrict__ x){
    int i = blockIdx.x*256 + threadIdx.x;
    ((float4*)g_cur)[i] = ((const float4*)x)[i];
}
__global__ void k_copy_out(float* __restrict__ out){
    int i = blockIdx.x*256 + threadIdx.x;
    ((float4*)out)[i] = ((const float4*)g_cur)[i];
}
__global__ void k_mix(){
    int i = blockIdx.x*256 + threadIdx.x;
    float gm = g_gm;
    float4 c = ((const float4*)g_cur)[i];
    float4 xo = ((const float4*)g_xo)[i];
    c.x += gm*(xo.x-c.x); c.y += gm*(xo.y-c.y);
    c.z += gm*(xo.z-c.z); c.w += gm*(xo.w-c.w);
    ((float4*)g_cur)[i] = c;
}

// mean over T: two stage
__global__ void k_meanT_part(const float* __restrict__ in){
    int b = blockIdx.x, c = blockIdx.y;           // c in [0,32)
    int t0 = c*32;
    for(int d = threadIdx.x; d < DD; d += 256){
        float s = 0.f;
        for(int t = t0; t < t0+32; t++) s += in[((size_t)(b*TT+t))*DD + d];
        g_part[(size_t)(b*32+c)*DD + d] = s;
    }
}
__global__ void k_meanT_reduce(){
    int b = blockIdx.x;
    for(int d = threadIdx.x; d < DD; d += 256){
        float s = 0.f;
        for(int c = 0; c < 32; c++) s += g_part[(size_t)(b*32+c)*DD + d];
        g_ctxm[b*DD + d] = s*(1.0f/TT);
    }
}

// ctx = ctxm @ ctx_w + ctx_b  (4 x 1024)
__global__ void k_ctx(const float* __restrict__ W, const float* __restrict__ bias){
    int b = blockIdx.x;
    int n = blockIdx.y*256 + threadIdx.x;
    const float* xv = &g_ctxm[b*DD];
    float s = bias[n];
    for(int k = 0; k < DD; k++) s += xv[k]*W[(size_t)k*DD + n];
    g_ctx[b*DD + n] = s;
}

// router: warp/adj/direct/gate_scores + top-3
__global__ void k_router(const float* __restrict__ summaries, const float* __restrict__ base_adj,
                         const float* __restrict__ warp_w, const float* __restrict__ warp_b,
                         const float* __restrict__ gate_w, const float* __restrict__ gate_b,
                         float* __restrict__ out_gs, float* __restrict__ out_adj,
                         float* __restrict__ out_mh){
    __shared__ float s_warp[BB][64];
    __shared__ float s_dir[BB][RR];
    __shared__ float s_gl[BB][RR];
    __shared__ float s_gs[BB][RR];
    int tid = threadIdx.x;
    {   int b = tid/64, c = tid%64;
        const float* xv = &g_ctx[b*DD];
        float s = warp_b[c];
        for(int k = 0; k < DD; k++) s += xv[k]*warp_w[(size_t)k*64 + c];
        s_warp[b][c] = s*0.1f;
    }
    if(tid < 32){
        int b = tid/8, r = tid%8;
        const float* xv = &g_ctx[b*DD];
        float s = 0.f;
        for(int k = 0; k < DD; k++) s += xv[k]*summaries[r*DD + k];
        s_dir[b][r] = s;
    } else if(tid < 64){
        int t = tid-32; int b = t/8, r = t%8;
        const float* xv = &g_ctx[b*DD];
        float s = gate_b[r];
        for(int k = 0; k < DD; k++) s += xv[k]*gate_w[k*RR + r];
        s_gl[b][r] = s;
    }
    __syncthreads();
    if(tid < 32){
        int b = tid/8, i = tid%8;
        float v[8]; float mx = -1e30f;
        for(int j = 0; j < 8; j++){ v[j] = base_adj[i*8+j] + s_warp[b][i*8+j]; mx = fmaxf(mx, v[j]); }
        float sum = 0.f;
        for(int j = 0; j < 8; j++){ v[j] = expf(v[j]-mx); sum += v[j]; }
        float inv = 1.0f/sum;
        float boost = 0.f;
        for(int j = 0; j < 8; j++){
            float a = v[j]*inv;
            out_adj[(b*8+i)*8 + j] = a;
            boost += a*s_dir[b][j];
        }
        float gs = 1.0f/(1.0f+expf(-(s_gl[b][i]+boost)*0.5f));
        out_gs[b*8+i] = gs;
        s_gs[b][i] = gs;
    }
    __syncthreads();
    if(tid == 0){
        float m[RR];
        for(int r = 0; r < 8; r++) m[r] = 0.25f*(s_gs[0][r]+s_gs[1][r]+s_gs[2][r]+s_gs[3][r]);
        for(int h = 0; h < 3; h++){
            int best = 0; float bv = -1e30f;
            for(int r = 0; r < 8; r++) if(m[r] > bv){ bv = m[r]; best = r; }
            g_idx[h] = best; m[best] = -1e30f;
        }
        out_mh[0] = 3.0f;
    }
}

// gate MLP stage 1
__global__ void k_g1(const float* __restrict__ g1_w, const float* __restrict__ g1_b, int hop){
    int room = g_idx[hop];
    int b = blockIdx.x, n = threadIdx.x;   // 256 threads
    const float* W = g1_w + (size_t)room*DD*256;
    const float* xv = &g_ctxm[b*DD];
    float s = g1_b[room*256 + n];
    for(int k = 0; k < DD; k++) s += xv[k]*W[(size_t)k*256 + n];
    g_h1[b*256 + n] = geluf(s);
}
// gate MLP stage 2 + gm
__global__ void k_g2(const float* __restrict__ g2_w, const float* __restrict__ g2_b, int hop){
    int room = g_idx[hop];
    __shared__ float red[256];
    int tid = threadIdx.x;
    int b = tid/64, lane = tid%64;
    const float* W = g2_w + room*256;
    float s = 0.f;
    for(int k = lane; k < 256; k += 64) s += g_h1[b*256 + k]*W[k];
    red[tid] = s; __syncthreads();
    for(int off = 32; off >= 1; off >>= 1){
        if(lane < off) red[tid] += red[tid+off];
        __syncthreads();
    }
    if(lane == 0){
        float gate = 1.0f/(1.0f+expf(-(red[tid]+g2_b[room])));
        g_gate[b] = gate;
    }
    __syncthreads();
    if(tid == 0) g_gm = 0.25f*(g_gate[0]+g_gate[1]+g_gate[2]+g_gate[3]);
}

// layernorm (optionally pre-scaled by gate[b]); per-room gamma/beta
__global__ void __launch_bounds__(256) k_ln(const float* __restrict__ in,
                     const float* __restrict__ gb, const float* __restrict__ bb,
                     int hop, const float* __restrict__ gate, float* __restrict__ out){
    int row = blockIdx.x; int b = row >> 10;
    int room = (hop >= 0) ? g_idx[hop] : 0;
    float sc = gate ? gate[b] : 1.0f;
    float4 v = ((const float4*)(in + (size_t)row*DD))[threadIdx.x];
    v.x *= sc; v.y *= sc; v.z *= sc; v.w *= sc;
    __shared__ float rs[256], rq[256];
    rs[threadIdx.x] = v.x+v.y+v.z+v.w;
    rq[threadIdx.x] = v.x*v.x+v.y*v.y+v.z*v.z+v.w*v.w;
    __syncthreads();
    for(int off = 128; off >= 1; off >>= 1){
        if(threadIdx.x < off){ rs[threadIdx.x] += rs[threadIdx.x+off]; rq[threadIdx.x] += rq[threadIdx.x+off]; }
        __syncthreads();
    }
    float mean = rs[0]*(1.0f/DD);
    float var  = rq[0]*(1.0f/DD) - mean*mean;
    float inv  = rsqrtf(var + 1e-5f);
    float4 g4 = ((const float4*)(gb + (size_t)room*DD))[threadIdx.x];
    float4 b4 = ((const float4*)(bb + (size_t)room*DD))[threadIdx.x];
    float4 o4;
    o4.x = (v.x-mean)*inv*g4.x + b4.x;
    o4.y = (v.y-mean)*inv*g4.y + b4.y;
    o4.z = (v.z-mean)*inv*g4.z + b4.z;
    o4.w = (v.w-mean)*inv*g4.w + b4.w;
    ((float4*)(out + (size_t)row*DD))[threadIdx.x] = o4;
}

// ---------------- tf32x3 tensor-core GEMM ----------------
// C[M,N] = A[M,K] @ W[K,N] + bias, opt gelu, opt residual (per-batch scale).
// Tile 128x128, BK=32, 256 threads (8 warps 4x2), register prefetch.
__global__ void __launch_bounds__(256) k_gemm_mma(const float* __restrict__ A,
        const float* __restrict__ Wb, const float* __restrict__ bbase,
        const float* __restrict__ res, const float* __restrict__ rscale,
        float* __restrict__ C, int N, int K, int hop,
        long wstr, long bstr, int act){
    int room = (hop >= 0) ? g_idx[hop] : 0;
    const float* W    = Wb    + (size_t)room*wstr;
    const float* bias = bbase + (size_t)room*bstr;
    __shared__ float As[128][36];
    __shared__ float Bs[32][136];
    int tid = threadIdx.x;
    int bm = blockIdx.y, bn = blockIdx.x;
    int warp = tid>>5, lane = tid&31;
    int g = lane>>2, t = lane&3;
    int wm = warp>>1, wn = warp&1;

    int arow = tid>>3, ac = (tid&7)*4;          // A: 32 rows x 8 f4, x4 iters
    int brow = tid>>5, bc = (tid&31)*4;         // B: 8 rows x 32 f4, x4 iters
    const float* Abase = A + (size_t)(bm*128 + arow)*K + ac;
    const float* Wbase = W + (size_t)brow*N + bn*128 + bc;

    float acc[2][8][4] = {};
    float4 pa[4], pb[4];
    #pragma unroll
    for(int i = 0; i < 4; i++) pa[i] = *(const float4*)(Abase + (size_t)(i*32)*K);
    #pragma unroll
    for(int i = 0; i < 4; i++) pb[i] = *(const float4*)(Wbase + (size_t)(i*8)*N);

    for(int k0 = 0; k0 < K; k0 += 32){
        #pragma unroll
        for(int i = 0; i < 4; i++) *(float4*)&As[arow + i*32][ac] = pa[i];
        #pragma unroll
        for(int i = 0; i < 4; i++) *(float4*)&Bs[brow + i*8][bc] = pb[i];
        __syncthreads();
        if(k0 + 32 < K){
            #pragma unroll
            for(int i = 0; i < 4; i++) pa[i] = *(const float4*)(Abase + (size_t)(i*32)*K + k0 + 32);
            #pragma unroll
            for(int i = 0; i < 4; i++) pb[i] = *(const float4*)(Wbase + (size_t)(k0 + 32 + i*8)*N);
        }
        #pragma unroll
        for(int kk = 0; kk < 32; kk += 8){
            uint32_t ah[2][4], al[2][4];
            #pragma unroll
            for(int mt = 0; mt < 2; mt++){
                int m0 = wm*32 + mt*16;
                split_tf(As[m0+g  ][kk+t  ], ah[mt][0], al[mt][0]);
                split_tf(As[m0+g+8][kk+t  ], ah[mt][1], al[mt][1]);
                split_tf(As[m0+g  ][kk+t+4], ah[mt][2], al[mt][2]);
                split_tf(As[m0+g+8][kk+t+4], ah[mt][3], al[mt][3]);
            }
            #pragma unroll
            for(int nt = 0; nt < 8; nt++){
                int n0 = wn*64 + nt*8 + g;
                uint32_t bh0, bl0, bh1, bl1;
                split_tf(Bs[kk+t  ][n0], bh0, bl0);
                split_tf(Bs[kk+t+4][n0], bh1, bl1);
                #pragma unroll
                for(int mt = 0; mt < 2; mt++){
                    mma_tf32(acc[mt][nt], ah[mt][0],ah[mt][1],ah[mt][2],ah[mt][3], bh0, bh1);
                    mma_tf32(acc[mt][nt], ah[mt][0],ah[mt][1],ah[mt][2],ah[mt][3], bl0, bl1);
                    mma_tf32(acc[mt][nt], al[mt][0],al[mt][1],al[mt][2],al[mt][3], bh0, bh1);
                }
            }
        }
        __syncthreads();
    }

    #pragma unroll
    for(int mt = 0; mt < 2; mt++){
        int row = bm*128 + wm*32 + mt*16 + g;
        #pragma unroll
        for(int nt = 0; nt < 8; nt++){
            int col = bn*128 + wn*64 + nt*8 + 2*t;
            float2 bi = *(const float2*)&bias[col];
            float v0 = acc[mt][nt][0] + bi.x;
            float v1 = acc[mt][nt][1] + bi.y;
            float v2 = acc[mt][nt][2] + bi.x;
            float v3 = acc[mt][nt][3] + bi.y;
            if(act == 1){
                v0 = geluf(v0); v1 = geluf(v1); v2 = geluf(v2); v3 = geluf(v3);
            }
            if(res){
                float sc = rscale ? rscale[row>>10] : 1.0f;
                float2 r0 = *(const float2*)&res[(size_t)row*N + col];
                float2 r1 = *(const float2*)&res[(size_t)(row+8)*N + col];
                v0 += r0.x*sc; v1 += r0.y*sc; v2 += r1.x*sc; v3 += r1.y*sc;
            }
            *(float2*)&C[(size_t)row*N + col]     = make_float2(v0, v1);
            *(float2*)&C[(size_t)(row+8)*N + col] = make_float2(v2, v3);
        }
    }
}

// ---------------- attention scores (tf32x3) ----------------
// s[bh,i,j] = q_i . k_j / 8, lower tiles only. 64x64 per block, 128 thr (2x2 warps).
__global__ void __launch_bounds__(128) k_scores_mma(const float* __restrict__ q, const float* __restrict__ kx){
    int ti = blockIdx.x, tj = blockIdx.y;
    if(tj > ti) return;
    int bh = blockIdx.z; int b = bh>>4, h = bh&15;
    __shared__ float Qs[64][68];
    __shared__ float Ks[64][72];   // Ks[dh][key]
    int tid = threadIdx.x;
    int warp = tid>>5, lane = tid&31;
    int g = lane>>2, t = lane&3;
    int wm = warp>>1, wn = warp&1;

    // load Q natural: 8 rows per thread group
    int qrow = tid>>4, qc = (tid&15)*4;
    const float* qbase = q + (size_t)(b*TT + ti*64 + qrow)*DD + h*64 + qc;
    #pragma unroll
    for(int i = 0; i < 8; i++)
        *(float4*)&Qs[qrow + i*8][qc] = *(const float4*)(qbase + (size_t)(i*8)*DD);
    // load K transposed: lane-per-key so smem stores are conflict-free
    int key = tid&63, ch = (tid>>6)*8;
    const float* kp = kx + (size_t)(b*TT + tj*64 + key)*DD + h*64;
    #pragma unroll
    for(int i = 0; i < 8; i++){
        float4 v = *(const float4*)(kp + (ch+i)*4);
        int c = (ch+i)*4;
        Ks[c+0][key] = v.x; Ks[c+1][key] = v.y; Ks[c+2][key] = v.z; Ks[c+3][key] = v.w;
    }
    __syncthreads();

    float acc[2][4][4] = {};
    #pragma unroll
    for(int kk = 0; kk < 64; kk += 8){
        uint32_t ah[2][4], al[2][4];
        #pragma unroll
        for(int mt = 0; mt < 2; mt++){
            int m0 = wm*32 + mt*16;
            split_tf(Qs[m0+g  ][kk+t  ], ah[mt][0], al[mt][0]);
            split_tf(Qs[m0+g+8][kk+t  ], ah[mt][1], al[mt][1]);
            split_tf(Qs[m0+g  ][kk+t+4], ah[mt][2], al[mt][2]);
            split_tf(Qs[m0+g+8][kk+t+4], ah[mt][3], al[mt][3]);
        }
        #pragma unroll
        for(int nt = 0; nt < 4; nt++){
            int n0 = wn*32 + nt*8 + g;
            uint32_t bh0, bl0, bh1, bl1;
            split_tf(Ks[kk+t  ][n0], bh0, bl0);
            split_tf(Ks[kk+t+4][n0], bh1, bl1);
            #pragma unroll
            for(int mt = 0; mt < 2; mt++){
                mma_tf32(acc[mt][nt], ah[mt][0],ah[mt][1],ah[mt][2],ah[mt][3], bh0, bh1);
                mma_tf32(acc[mt][nt], ah[mt][0],ah[mt][1],ah[mt][2],ah[mt][3], bl0, bl1);
                mma_tf32(acc[mt][nt], al[mt][0],al[mt][1],al[mt][2],al[mt][3], bh0, bh1);
            }
        }
    }
    #pragma unroll
    for(int mt = 0; mt < 2; mt++){
        int row = ti*64 + wm*32 + mt*16 + g;
        #pragma unroll
        for(int nt = 0; nt < 4; nt++){
            int col = tj*64 + wn*32 + nt*8 + 2*t;
            float* sp = g_attn + ((size_t)bh*TT + row)*TT + col;
            *(float2*)sp = make_float2(acc[mt][nt][0]*0.125f, acc[mt][nt][1]*0.125f);
            *(float2*)(sp + (size_t)8*TT) = make_float2(acc[mt][nt][2]*0.125f, acc[mt][nt][3]*0.125f);
        }
    }
}

// row softmax with causal truncation + zero fill
__global__ void __launch_bounds__(128) k_softmax(){
    int row = blockIdx.x;              // bh*T + i
    int i = row & (TT-1);
    float* p = g_attn + (size_t)row*TT;
    int len = i+1, tid = threadIdx.x;
    __shared__ float red[128];
    float mx = -1e30f;
    for(int j = tid; j < len; j += 128) mx = fmaxf(mx, p[j]);
    red[tid] = mx; __syncthreads();
    for(int off = 64; off >= 1; off >>= 1){
        if(tid < off) red[tid] = fmaxf(red[tid], red[tid+off]);
        __syncthreads();
    }
    mx = red[0]; __syncthreads();
    float s = 0.f;
    for(int j = tid; j < len; j += 128){ float e = expf(p[j]-mx); p[j] = e; s += e; }
    red[tid] = s; __syncthreads();
    for(int off = 64; off >= 1; off >>= 1){
        if(tid < off) red[tid] += red[tid+off];
        __syncthreads();
    }
    float inv = 1.0f/red[0];
    for(int j = tid; j < len; j += 128) p[j] *= inv;
    for(int j = len + tid; j < TT; j += 128) p[j] = 0.f;
}

// o = a @ v per (bh), causal K-truncation (tf32x3)
__global__ void __launch_bounds__(128) k_av_mma(const float* __restrict__ v, float* __restrict__ o){
    int ti = blockIdx.x; int bh = blockIdx.y;
    int b = bh>>4, h = bh&15;
    __shared__ float Ps[64][68];   // probs [q][key]
    __shared__ float Vs[64][72];   // v     [key][dh]
    int tid = threadIdx.x;
    int warp = tid>>5, lane = tid&31;
    int g = lane>>2, t = lane&3;
    int wm = warp>>1, wn = warp&1;
    int prow = tid>>4, pc = (tid&15)*4;

    float acc[2][4][4] = {};
    for(int kt = 0; kt <= ti; kt++){
        const float* pbase = g_attn + ((size_t)bh*TT + ti*64 + prow)*TT + kt*64 + pc;
        const float* vbase = v + (size_t)(b*TT + kt*64 + prow)*DD + h*64 + pc;
        #pragma unroll
        for(int i = 0; i < 8; i++)
            *(float4*)&Ps[prow + i*8][pc] = *(const float4*)(pbase + (size_t)(i*8)*TT);
        #pragma unroll
        for(int i = 0; i < 8; i++)
            *(float4*)&Vs[prow + i*8][pc] = *(const float4*)(vbase + (size_t)(i*8)*DD);
        __syncthreads();
        #pragma unroll
        for(int kk = 0; kk < 64; kk += 8){
            uint32_t ah[2][4], al[2][4];
            #pragma unroll
            for(int mt = 0; mt < 2; mt++){
                int m0 = wm*32 + mt*16;
                split_tf(Ps[m0+g  ][kk+t  ], ah[mt][0], al[mt][0]);
                split_tf(Ps[m0+g+8][kk+t  ], ah[mt][1], al[mt][1]);
                split_tf(Ps[m0+g  ][kk+t+4], ah[mt][2], al[mt][2]);
                split_tf(Ps[m0+g+8][kk+t+4], ah[mt][3], al[mt][3]);
            }
            #pragma unroll
            for(int nt = 0; nt < 4; nt++){
                int n0 = wn*32 + nt*8 + g;
                uint32_t bh0, bl0, bh1, bl1;
                split_tf(Vs[kk+t  ][n0], bh0, bl0);
                split_tf(Vs[kk+t+4][n0], bh1, bl1);
                #pragma unroll
                for(int mt = 0; mt < 2; mt++){
                    mma_tf32(acc[mt][nt], ah[mt][0],ah[mt][1],ah[mt][2],ah[mt][3], bh0, bh1);
                    mma_tf32(acc[mt][nt], ah[mt][0],ah[mt][1],ah[mt][2],ah[mt][3], bl0, bl1);
                    mma_tf32(acc[mt][nt], al[mt][0],al[mt][1],al[mt][2],al[mt][3], bh0, bh1);
                }
            }
        }
        __syncthreads();
    }
    #pragma unroll
    for(int mt = 0; mt < 2; mt++){
        int row = ti*64 + wm*32 + mt*16 + g;
        #pragma unroll
        for(int nt = 0; nt < 4; nt++){
            int col = wn*32 + nt*8 + 2*t;
            float* op = o + (size_t)(b*TT + row)*DD + h*64 + col;
            *(float2*)op = make_float2(acc[mt][nt][0], acc[mt][nt][1]);
            *(float2*)(op + (size_t)8*DD) = make_float2(acc[mt][nt][2], acc[mt][nt][3]);
        }
    }
}

extern "C" void kernel_launch(void* const* d_in, const int* in_sizes, int n_in,
                              void* d_out, int out_size){
    const float* x         = (const float*)d_in[0];
    const float* summaries = (const float*)d_in[1];
    const float* ctx_w     = (const float*)d_in[2];
    const float* ctx_b     = (const float*)d_in[3];
    const float* base_adj  = (const float*)d_in[4];
    const float* warp_w    = (const float*)d_in[5];
    const float* warp_b    = (const float*)d_in[6];
    const float* gate_w    = (const float*)d_in[7];
    const float* gate_b    = (const float*)d_in[8];
    const float* g1_w      = (const float*)d_in[9];
    const float* g1_b      = (const float*)d_in[10];
    const float* g2_w      = (const float*)d_in[11];
    const float* g2_b      = (const float*)d_in[12];
    const float* ln1_g     = (const float*)d_in[13];
    const float* ln1_b     = (const float*)d_in[14];
    const float* wq        = (const float*)d_in[15];
    const float* bq        = (const float*)d_in[16];
    const float* wk        = (const float*)d_in[17];
    const float* bk        = (const float*)d_in[18];
    const float* wv        = (const float*)d_in[19];
    const float* bv        = (const float*)d_in[20];
    const float* wo        = (const float*)d_in[21];
    const float* bo        = (const float*)d_in[22];
    const float* ln2_g     = (const float*)d_in[23];
    const float* ln2_b     = (const float*)d_in[24];
    const float* ff1_w     = (const float*)d_in[25];
    const float* ff1_b     = (const float*)d_in[26];
    const float* ff2_w     = (const float*)d_in[27];
    const float* ff2_b     = (const float*)d_in[28];
    float* out = (float*)d_out;

    float *p_cur, *p_norm, *p_q, *p_k, *p_v, *p_o, *p_xo, *p_mid, *p_gate;
    cudaGetSymbolAddress((void**)&p_cur,  g_cur);
    cudaGetSymbolAddress((void**)&p_norm, g_norm);
    cudaGetSymbolAddress((void**)&p_q,    g_q);
    cudaGetSymbolAddress((void**)&p_k,    g_k);
    cudaGetSymbolAddress((void**)&p_v,    g_v);
    cudaGetSymbolAddress((void**)&p_o,    g_o);
    cudaGetSymbolAddress((void**)&p_xo,   g_xo);
    cudaGetSymbolAddress((void**)&p_mid,  g_mid);
    cudaGetSymbolAddress((void**)&p_gate, g_gate);

    const int CP_BLKS = BTD/4/256;

    // init working buffer
    k_copy_in<<<CP_BLKS,256>>>(x);

    // ---- router ----
    k_meanT_part<<<dim3(BB,32),256>>>(x);
    k_meanT_reduce<<<BB,256>>>();
    k_ctx<<<dim3(BB,4),256>>>(ctx_w, ctx_b);
    k_router<<<1,256>>>(summaries, base_adj, warp_w, warp_b, gate_w, gate_b,
                        out + BTD, out + BTD + 32, out + BTD + 32 + 256);

    // ---- 3 hops ----
    for(int hop = 0; hop < 3; hop++){
        k_meanT_part<<<dim3(BB,32),256>>>(p_cur);
        k_meanT_reduce<<<BB,256>>>();
        k_g1<<<BB,256>>>(g1_w, g1_b, hop);
        k_g2<<<1,256>>>(g2_w, g2_b, hop);
        // ln1(xg)
        k_ln<<<BT,256>>>(p_cur, ln1_g, ln1_b, hop, p_gate, p_norm);
        // q,k,v
        k_gemm_mma<<<dim3(8,32),256>>>(p_norm, wq, bq, nullptr, nullptr, p_q, DD, DD, hop, (long)DD*DD, DD, 0);
        k_gemm_mma<<<dim3(8,32),256>>>(p_norm, wk, bk, nullptr, nullptr, p_k, DD, DD, hop, (long)DD*DD, DD, 0);
        k_gemm_mma<<<dim3(8,32),256>>>(p_norm, wv, bv, nullptr, nullptr, p_v, DD, DD, hop, (long)DD*DD, DD, 0);
        // attention
        k_scores_mma<<<dim3(16,16,BB*HH),128>>>(p_q, p_k);
        k_softmax<<<BB*HH*TT,128>>>();
        k_av_mma<<<dim3(16,BB*HH),128>>>(p_v, p_o);
        // xo = xg + o@wo + bo
        k_gemm_mma<<<dim3(8,32),256>>>(p_o, wo, bo, p_cur, p_gate, p_xo, DD, DD, hop, (long)DD*DD, DD, 0);
        // ffn
        k_ln<<<BT,256>>>(p_xo, ln2_g, ln2_b, hop, nullptr, p_norm);
        k_gemm_mma<<<dim3(32,32),256>>>(p_norm, ff1_w, ff1_b, nullptr, nullptr, p_mid, DFF, DD, hop, (long)DD*DFF, DFF, 1);
        k_gemm_mma<<<dim3(8,32),256>>>(p_mid, ff2_w, ff2_b, p_xo, nullptr, p_xo, DD, DFF, hop, (long)DFF*DD, DD, 0);
        // cur = cur + gm*(xo - cur)
        k_mix<<<CP_BLKS,256>>>();
    }

    k_copy_out<<<CP_BLKS,256>>>(out);
}

// round 4
// speedup vs baseline: 2.3448x; 1.5623x over previous
#include <cuda_runtime.h>
#include <cuda_bf16.h>
#include <math.h>
#include <stdint.h>

#define BB 4
#define TT 1024
#define DD 1024
#define HH 16
#define DHH 64
#define DFF 4096
#define RR 8
#define BT (BB*TT)          // 4096
#define BTD (BB*TT*DD)      // 4194304

// ---------------- device scratch ----------------
__device__ float g_cur[BTD];
__device__ float g_norm[BTD];
__device__ float g_q[BTD];
__device__ float g_k[BTD];
__device__ float g_v[BTD];
__device__ float g_o[BTD];
__device__ float g_xo[BTD];
__device__ float g_attn[(size_t)BB*HH*TT*TT];
__device__ float g_mid[BB*TT*DFF];
__device__ float g_part[BB*32*DD];
__device__ float g_ctxm[BB*DD];
__device__ float g_ctx[BB*DD];
__device__ float g_h1[BB*256];
__device__ float g_gate[BB];
__device__ float g_gm;
__device__ int   g_idx[3];

__device__ __forceinline__ float geluf(float x){
    return 0.5f*x*(1.0f+erff(x*0.7071067811865476f));
}

// ---------------- bf16 split helpers ----------------
__device__ __forceinline__ void split2(float x, float y, uint32_t &hi, uint32_t &lo){
    __nv_bfloat16 xh = __float2bfloat16_rn(x);
    __nv_bfloat16 yh = __float2bfloat16_rn(y);
    __nv_bfloat162 h; h.x = xh; h.y = yh;
    __nv_bfloat162 l; l.x = __float2bfloat16_rn(x - __bfloat162float(xh));
    l.y = __float2bfloat16_rn(y - __bfloat162float(yh));
    hi = *(uint32_t*)&h; lo = *(uint32_t*)&l;
}
__device__ __forceinline__ void mma_bf16(float* c, uint32_t a0, uint32_t a1, uint32_t a2, uint32_t a3,
                                         uint32_t b0, uint32_t b1){
    asm volatile("mma.sync.aligned.m16n8k16.row.col.f32.bf16.bf16.f32 "
        "{%0,%1,%2,%3},{%4,%5,%6,%7},{%8,%9},{%0,%1,%2,%3};"
        : "+f"(c[0]), "+f"(c[1]), "+f"(c[2]), "+f"(c[3])
        : "r"(a0), "r"(a1), "r"(a2), "r"(a3), "r"(b0), "r"(b1));
}
#define MMA3(accp, AH, AL, BH0, BH1, BL0, BL1) \
    mma_bf16(accp, AH[0],AH[1],AH[2],AH[3], BH0, BH1); \
    mma_bf16(accp, AH[0],AH[1],AH[2],AH[3], BL0, BL1); \
    mma_bf16(accp, AL[0],AL[1],AL[2],AL[3], BH0, BH1);

// ---------------- utility kernels ----------------
__global__ void k_copy_in(const float* __restrict__ x){
    int i = blockIdx.x*256 + threadIdx.x;
    ((float4*)g_cur)[i] = ((const float4*)x)[i];
}
__global__ void k_copy_out(float* __restrict__ out){
    int i = blockIdx.x*256 + threadIdx.x;
    ((float4*)out)[i] = ((const float4*)g_cur)[i];
}
__global__ void k_mix(){
    int i = blockIdx.x*256 + threadIdx.x;
    float gm = g_gm;
    float4 c = ((const float4*)g_cur)[i];
    float4 xo = ((const float4*)g_xo)[i];
    c.x += gm*(xo.x-c.x); c.y += gm*(xo.y-c.y);
    c.z += gm*(xo.z-c.z); c.w += gm*(xo.w-c.w);
    ((float4*)g_cur)[i] = c;
}

// mean over T: two stage
__global__ void k_meanT_part(const float* __restrict__ in){
    int b = blockIdx.x, c = blockIdx.y;
    int t0 = c*32;
    for(int d = threadIdx.x; d < DD; d += 256){
        float s = 0.f;
        for(int t = t0; t < t0+32; t++) s += in[((size_t)(b*TT+t))*DD + d];
        g_part[(size_t)(b*32+c)*DD + d] = s;
    }
}
__global__ void k_meanT_reduce(){
    int b = blockIdx.x;
    for(int d = threadIdx.x; d < DD; d += 256){
        float s = 0.f;
        for(int c = 0; c < 32; c++) s += g_part[(size_t)(b*32+c)*DD + d];
        g_ctxm[b*DD + d] = s*(1.0f/TT);
    }
}

// ctx = ctxm @ ctx_w + ctx_b : split-K GEMV, grid (BB,32), 128 thr
__global__ void k_ctx(const float* __restrict__ W, const float* __restrict__ bias){
    int b = blockIdx.x; int n0 = blockIdx.y*32;
    int lane = threadIdx.x & 31, q = threadIdx.x >> 5;
    const float* xv = &g_ctxm[b*DD];
    float s = 0.f;
    int k0 = q*256;
    for(int k = k0; k < k0+256; k++) s += xv[k]*W[(size_t)k*DD + n0 + lane];
    __shared__ float red[4][32];
    red[q][lane] = s; __syncthreads();
    if(q == 0)
        g_ctx[b*DD + n0 + lane] = red[0][lane]+red[1][lane]+red[2][lane]+red[3][lane] + bias[n0+lane];
}

// router
__global__ void k_router(const float* __restrict__ summaries, const float* __restrict__ base_adj,
                         const float* __restrict__ warp_w, const float* __restrict__ warp_b,
                         const float* __restrict__ gate_w, const float* __restrict__ gate_b,
                         float* __restrict__ out_gs, float* __restrict__ out_adj,
                         float* __restrict__ out_mh){
    __shared__ float s_warp[BB][64];
    __shared__ float s_dir[BB][RR];
    __shared__ float s_gl[BB][RR];
    __shared__ float s_gs[BB][RR];
    int tid = threadIdx.x;
    {   int b = tid/64, c = tid%64;
        const float* xv = &g_ctx[b*DD];
        float s = warp_b[c];
        for(int k = 0; k < DD; k++) s += xv[k]*warp_w[(size_t)k*64 + c];
        s_warp[b][c] = s*0.1f;
    }
    if(tid < 32){
        int b = tid/8, r = tid%8;
        const float* xv = &g_ctx[b*DD];
        float s = 0.f;
        for(int k = 0; k < DD; k++) s += xv[k]*summaries[r*DD + k];
        s_dir[b][r] = s;
    } else if(tid < 64){
        int t = tid-32; int b = t/8, r = t%8;
        const float* xv = &g_ctx[b*DD];
        float s = gate_b[r];
        for(int k = 0; k < DD; k++) s += xv[k]*gate_w[k*RR + r];
        s_gl[b][r] = s;
    }
    __syncthreads();
    if(tid < 32){
        int b = tid/8, i = tid%8;
        float v[8]; float mx = -1e30f;
        for(int j = 0; j < 8; j++){ v[j] = base_adj[i*8+j] + s_warp[b][i*8+j]; mx = fmaxf(mx, v[j]); }
        float sum = 0.f;
        for(int j = 0; j < 8; j++){ v[j] = expf(v[j]-mx); sum += v[j]; }
        float inv = 1.0f/sum;
        float boost = 0.f;
        for(int j = 0; j < 8; j++){
            float a = v[j]*inv;
            out_adj[(b*8+i)*8 + j] = a;
            boost += a*s_dir[b][j];
        }
        float gs = 1.0f/(1.0f+expf(-(s_gl[b][i]+boost)*0.5f));
        out_gs[b*8+i] = gs;
        s_gs[b][i] = gs;
    }
    __syncthreads();
    if(tid == 0){
        float m[RR];
        for(int r = 0; r < 8; r++) m[r] = 0.25f*(s_gs[0][r]+s_gs[1][r]+s_gs[2][r]+s_gs[3][r]);
        for(int h = 0; h < 3; h++){
            int best = 0; float bv = -1e30f;
            for(int r = 0; r < 8; r++) if(m[r] > bv){ bv = m[r]; best = r; }
            g_idx[h] = best; m[best] = -1e30f;
        }
        out_mh[0] = 3.0f;
    }
}

// gate MLP
__global__ void k_g1(const float* __restrict__ g1_w, const float* __restrict__ g1_b, int hop){
    int room = g_idx[hop];
    int b = blockIdx.x, n = threadIdx.x;
    const float* W = g1_w + (size_t)room*DD*256;
    const float* xv = &g_ctxm[b*DD];
    float s = g1_b[room*256 + n];
    for(int k = 0; k < DD; k++) s += xv[k]*W[(size_t)k*256 + n];
    g_h1[b*256 + n] = geluf(s);
}
__global__ void k_g2(const float* __restrict__ g2_w, const float* __restrict__ g2_b, int hop){
    int room = g_idx[hop];
    __shared__ float red[256];
    int tid = threadIdx.x;
    int b = tid/64, lane = tid%64;
    const float* W = g2_w + room*256;
    float s = 0.f;
    for(int k = lane; k < 256; k += 64) s += g_h1[b*256 + k]*W[k];
    red[tid] = s; __syncthreads();
    for(int off = 32; off >= 1; off >>= 1){
        if(lane < off) red[tid] += red[tid+off];
        __syncthreads();
    }
    if(lane == 0){
        float gate = 1.0f/(1.0f+expf(-(red[tid]+g2_b[room])));
        g_gate[b] = gate;
    }
    __syncthreads();
    if(tid == 0) g_gm = 0.25f*(g_gate[0]+g_gate[1]+g_gate[2]+g_gate[3]);
}

// layernorm
__global__ void __launch_bounds__(256) k_ln(const float* __restrict__ in,
                     const float* __restrict__ gb, const float* __restrict__ bb,
                     int hop, const float* __restrict__ gate, float* __restrict__ out){
    int row = blockIdx.x; int b = row >> 10;
    int room = (hop >= 0) ? g_idx[hop] : 0;
    float sc = gate ? gate[b] : 1.0f;
    float4 v = ((const float4*)(in + (size_t)row*DD))[threadIdx.x];
    v.x *= sc; v.y *= sc; v.z *= sc; v.w *= sc;
    __shared__ float rs[256], rq[256];
    rs[threadIdx.x] = v.x+v.y+v.z+v.w;
    rq[threadIdx.x] = v.x*v.x+v.y*v.y+v.z*v.z+v.w*v.w;
    __syncthreads();
    for(int off = 128; off >= 1; off >>= 1){
        if(threadIdx.x < off){ rs[threadIdx.x] += rs[threadIdx.x+off]; rq[threadIdx.x] += rq[threadIdx.x+off]; }
        __syncthreads();
    }
    float mean = rs[0]*(1.0f/DD);
    float var  = rq[0]*(1.0f/DD) - mean*mean;
    float inv  = rsqrtf(var + 1e-5f);
    float4 g4 = ((const float4*)(gb + (size_t)room*DD))[threadIdx.x];
    float4 b4 = ((const float4*)(bb + (size_t)room*DD))[threadIdx.x];
    float4 o4;
    o4.x = (v.x-mean)*inv*g4.x + b4.x;
    o4.y = (v.y-mean)*inv*g4.y + b4.y;
    o4.z = (v.z-mean)*inv*g4.z + b4.z;
    o4.w = (v.w-mean)*inv*g4.w + b4.w;
    ((float4*)(out + (size_t)row*DD))[threadIdx.x] = o4;
}

// ---------------- bf16x3 tensor-core GEMM ----------------
__global__ void __launch_bounds__(256) k_gemm_bf(const float* __restrict__ A,
        const float* __restrict__ Wb, const float* __restrict__ bbase,
        const float* __restrict__ res, const float* __restrict__ rscale,
        float* __restrict__ C, int N, int K, int hop,
        long wstr, long bstr, int act){
    int room = (hop >= 0) ? g_idx[hop] : 0;
    const float* W    = Wb    + (size_t)room*wstr;
    const float* bias = bbase + (size_t)room*bstr;
    __shared__ uint32_t Ah[128][20], Al[128][20];
    __shared__ uint32_t Bh[16][136], Bl[16][136];
    int tid = threadIdx.x;
    int bm = blockIdx.y, bn = blockIdx.x;
    int warp = tid>>5, lane = tid&31;
    int g = lane>>2, t = lane&3;
    int wm = warp>>1, wn = warp&1;

    int ar = tid>>3, ac4 = tid&7;           // A: 32 rows x 8 float4, x4 iters
    int bk2 = tid>>5, bn4 = tid&31;         // B: k2 rows, 32 float4 cols, x2 iters
    const float* Abase = A + (size_t)(bm*128 + ar)*K + ac4*4;
    const float* Wbase = W + (size_t)(bn*128) + bn4*4;

    float acc[2][8][4] = {};
    float4 pa[4], pb0[2], pb1[2];
    #pragma unroll
    for(int i = 0; i < 4; i++) pa[i] = *(const float4*)(Abase + (size_t)(i*32)*K);
    #pragma unroll
    for(int i = 0; i < 2; i++){
        int k2 = bk2 + 8*i;
        pb0[i] = *(const float4*)(Wbase + (size_t)(2*k2  )*N);
        pb1[i] = *(const float4*)(Wbase + (size_t)(2*k2+1)*N);
    }

    for(int k0 = 0; k0 < K; k0 += 32){
        #pragma unroll
        for(int i = 0; i < 4; i++){
            uint32_t h0,l0,h1,l1;
            split2(pa[i].x, pa[i].y, h0, l0);
            split2(pa[i].z, pa[i].w, h1, l1);
            int m = ar + 32*i;
            *(uint2*)&Ah[m][2*ac4] = make_uint2(h0, h1);
            *(uint2*)&Al[m][2*ac4] = make_uint2(l0, l1);
        }
        #pragma unroll
        for(int i = 0; i < 2; i++){
            int k2 = bk2 + 8*i;
            const float* r0 = (const float*)&pb0[i];
            const float* r1 = (const float*)&pb1[i];
            uint32_t h[4], l[4];
            #pragma unroll
            for(int j = 0; j < 4; j++) split2(r0[j], r1[j], h[j], l[j]);
            *(uint4*)&Bh[k2][bn4*4] = make_uint4(h[0],h[1],h[2],h[3]);
            *(uint4*)&Bl[k2][bn4*4] = make_uint4(l[0],l[1],l[2],l[3]);
        }
        __syncthreads();
        if(k0 + 32 < K){
            #pragma unroll
            for(int i = 0; i < 4; i++) pa[i] = *(const float4*)(Abase + (size_t)(i*32)*K + k0 + 32);
            #pragma unroll
            for(int i = 0; i < 2; i++){
                int k2 = bk2 + 8*i;
                pb0[i] = *(const float4*)(Wbase + (size_t)(k0 + 32 + 2*k2  )*N);
                pb1[i] = *(const float4*)(Wbase + (size_t)(k0 + 32 + 2*k2+1)*N);
            }
        }
        #pragma unroll
        for(int kk2 = 0; kk2 < 16; kk2 += 8){
            uint32_t ah[2][4], al[2][4];
            #pragma unroll
            for(int mt = 0; mt < 2; mt++){
                int m0 = wm*32 + mt*16;
                ah[mt][0] = Ah[m0+g  ][kk2+t  ]; al[mt][0] = Al[m0+g  ][kk2+t  ];
                ah[mt][1] = Ah[m0+g+8][kk2+t  ]; al[mt][1] = Al[m0+g+8][kk2+t  ];
                ah[mt][2] = Ah[m0+g  ][kk2+t+4]; al[mt][2] = Al[m0+g  ][kk2+t+4];
                ah[mt][3] = Ah[m0+g+8][kk2+t+4]; al[mt][3] = Al[m0+g+8][kk2+t+4];
            }
            #pragma unroll
            for(int nt = 0; nt < 8; nt++){
                int n0 = wn*64 + nt*8 + g;
                uint32_t bh0 = Bh[kk2+t  ][n0], bl0 = Bl[kk2+t  ][n0];
                uint32_t bh1 = Bh[kk2+t+4][n0], bl1 = Bl[kk2+t+4][n0];
                #pragma unroll
                for(int mt = 0; mt < 2; mt++){
                    MMA3(acc[mt][nt], ah[mt], al[mt], bh0, bh1, bl0, bl1);
                }
            }
        }
        __syncthreads();
    }

    #pragma unroll
    for(int mt = 0; mt < 2; mt++){
        int row = bm*128 + wm*32 + mt*16 + g;
        #pragma unroll
        for(int nt = 0; nt < 8; nt++){
            int col = bn*128 + wn*64 + nt*8 + 2*t;
            float2 bi = *(const float2*)&bias[col];
            float v0 = acc[mt][nt][0] + bi.x;
            float v1 = acc[mt][nt][1] + bi.y;
            float v2 = acc[mt][nt][2] + bi.x;
            float v3 = acc[mt][nt][3] + bi.y;
            if(act == 1){
                v0 = geluf(v0); v1 = geluf(v1); v2 = geluf(v2); v3 = geluf(v3);
            }
            if(res){
                float sc = rscale ? rscale[row>>10] : 1.0f;
                float2 r0 = *(const float2*)&res[(size_t)row*N + col];
                float2 r1 = *(const float2*)&res[(size_t)(row+8)*N + col];
                v0 += r0.x*sc; v1 += r0.y*sc; v2 += r1.x*sc; v3 += r1.y*sc;
            }
            *(float2*)&C[(size_t)row*N + col]     = make_float2(v0, v1);
            *(float2*)&C[(size_t)(row+8)*N + col] = make_float2(v2, v3);
        }
    }
}

// ---------------- attention scores (bf16x3) ----------------
__global__ void __launch_bounds__(128) k_scores_bf(const float* __restrict__ q, const float* __restrict__ kx){
    int ti = blockIdx.x, tj = blockIdx.y;
    if(tj > ti) return;
    int bh = blockIdx.z; int b = bh>>4, h = bh&15;
    __shared__ uint32_t Qh[64][36], Ql[64][36];
    __shared__ uint32_t Kh[64][36], Kl[64][36];
    int tid = threadIdx.x;
    int warp = tid>>5, lane = tid&31;
    int g = lane>>2, t = lane&3;
    int wm = warp>>1, wn = warp&1;

    int qr = tid>>4, qc4 = tid&15;
    const float* qbase = q  + (size_t)(b*TT + ti*64 + qr)*DD + h*64 + qc4*4;
    const float* kbase = kx + (size_t)(b*TT + tj*64 + qr)*DD + h*64 + qc4*4;
    #pragma unroll
    for(int i = 0; i < 8; i++){
        float4 v = *(const float4*)(qbase + (size_t)(i*8)*DD);
        uint32_t h0,l0,h1,l1;
        split2(v.x, v.y, h0, l0); split2(v.z, v.w, h1, l1);
        *(uint2*)&Qh[qr + i*8][2*qc4] = make_uint2(h0,h1);
        *(uint2*)&Ql[qr + i*8][2*qc4] = make_uint2(l0,l1);
        float4 w = *(const float4*)(kbase + (size_t)(i*8)*DD);
        split2(w.x, w.y, h0, l0); split2(w.z, w.w, h1, l1);
        *(uint2*)&Kh[qr + i*8][2*qc4] = make_uint2(h0,h1);
        *(uint2*)&Kl[qr + i*8][2*qc4] = make_uint2(l0,l1);
    }
    __syncthreads();

    float acc[2][4][4] = {};
    #pragma unroll
    for(int kk2 = 0; kk2 < 32; kk2 += 8){
        uint32_t ah[2][4], al[2][4];
        #pragma unroll
        for(int mt = 0; mt < 2; mt++){
            int m0 = wm*32 + mt*16;
            ah[mt][0] = Qh[m0+g  ][kk2+t  ]; al[mt][0] = Ql[m0+g  ][kk2+t  ];
            ah[mt][1] = Qh[m0+g+8][kk2+t  ]; al[mt][1] = Ql[m0+g+8][kk2+t  ];
            ah[mt][2] = Qh[m0+g  ][kk2+t+4]; al[mt][2] = Ql[m0+g  ][kk2+t+4];
            ah[mt][3] = Qh[m0+g+8][kk2+t+4]; al[mt][3] = Ql[m0+g+8][kk2+t+4];
        }
        #pragma unroll
        for(int nt = 0; nt < 4; nt++){
            int n0 = wn*32 + nt*8 + g;
            uint32_t bh0 = Kh[n0][kk2+t  ], bl0 = Kl[n0][kk2+t  ];
            uint32_t bh1 = Kh[n0][kk2+t+4], bl1 = Kl[n0][kk2+t+4];
            #pragma unroll
            for(int mt = 0; mt < 2; mt++){
                MMA3(acc[mt][nt], ah[mt], al[mt], bh0, bh1, bl0, bl1);
            }
        }
    }
    #pragma unroll
    for(int mt = 0; mt < 2; mt++){
        int row = ti*64 + wm*32 + mt*16 + g;
        #pragma unroll
        for(int nt = 0; nt < 4; nt++){
            int col = tj*64 + wn*32 + nt*8 + 2*t;
            float* sp = g_attn + ((size_t)bh*TT + row)*TT + col;
            *(float2*)sp = make_float2(acc[mt][nt][0]*0.125f, acc[mt][nt][1]*0.125f);
            *(float2*)(sp + (size_t)8*TT) = make_float2(acc[mt][nt][2]*0.125f, acc[mt][nt][3]*0.125f);
        }
    }
}

// row softmax with causal truncation + zero fill
__global__ void __launch_bounds__(128) k_softmax(){
    int row = blockIdx.x;
    int i = row & (TT-1);
    float* p = g_attn + (size_t)row*TT;
    int len = i+1, tid = threadIdx.x;
    __shared__ float red[128];
    float mx = -1e30f;
    for(int j = tid; j < len; j += 128) mx = fmaxf(mx, p[j]);
    red[tid] = mx; __syncthreads();
    for(int off = 64; off >= 1; off >>= 1){
        if(tid < off) red[tid] = fmaxf(red[tid], red[tid+off]);
        __syncthreads();
    }
    mx = red[0]; __syncthreads();
    float s = 0.f;
    for(int j = tid; j < len; j += 128){ float e = expf(p[j]-mx); p[j] = e; s += e; }
    red[tid] = s; __syncthreads();
    for(int off = 64; off >= 1; off >>= 1){
        if(tid < off) red[tid] += red[tid+off];
        __syncthreads();
    }
    float inv = 1.0f/red[0];
    for(int j = tid; j < len; j += 128) p[j] *= inv;
    for(int j = len + tid; j < TT; j += 128) p[j] = 0.f;
}

// o = a @ v per (bh), causal K-truncation (bf16x3)
__global__ void __launch_bounds__(128) k_av_bf(const float* __restrict__ v, float* __restrict__ o){
    int ti = blockIdx.x; int bh = blockIdx.y;
    int b = bh>>4, h = bh&15;
    __shared__ uint32_t Ph[64][36], Pl[64][36];
    __shared__ uint32_t Vh[32][72], Vl[32][72];
    int tid = threadIdx.x;
    int warp = tid>>5, lane = tid&31;
    int g = lane>>2, t = lane&3;
    int wm = warp>>1, wn = warp&1;
    int pr = tid>>4, pc4 = tid&15;
    int vk2 = tid>>4, vn4 = tid&15;

    float acc[2][4][4] = {};
    for(int kt = 0; kt <= ti; kt++){
        const float* pbase = g_attn + ((size_t)bh*TT + ti*64 + pr)*TT + kt*64 + pc4*4;
        #pragma unroll
        for(int i = 0; i < 8; i++){
            float4 pv = *(const float4*)(pbase + (size_t)(i*8)*TT);
            uint32_t h0,l0,h1,l1;
            split2(pv.x, pv.y, h0, l0); split2(pv.z, pv.w, h1, l1);
            *(uint2*)&Ph[pr + i*8][2*pc4] = make_uint2(h0,h1);
            *(uint2*)&Pl[pr + i*8][2*pc4] = make_uint2(l0,l1);
        }
        // FIX R3: cover all 32 k2 rows (i = 0..3), was 0..1 -> half of V uninitialized
        #pragma unroll
        for(int i = 0; i < 4; i++){
            int k2 = vk2 + 8*i;
            const float* v0 = v + (size_t)(b*TT + kt*64 + 2*k2  )*DD + h*64 + vn4*4;
            const float* v1 = v + (size_t)(b*TT + kt*64 + 2*k2+1)*DD + h*64 + vn4*4;
            float4 a4 = *(const float4*)v0;
            float4 b4 = *(const float4*)v1;
            const float* r0 = (const float*)&a4;
            const float* r1 = (const float*)&b4;
            uint32_t hh[4], ll[4];
            #pragma unroll
            for(int j = 0; j < 4; j++) split2(r0[j], r1[j], hh[j], ll[j]);
            *(uint4*)&Vh[k2][vn4*4] = make_uint4(hh[0],hh[1],hh[2],hh[3]);
            *(uint4*)&Vl[k2][vn4*4] = make_uint4(ll[0],ll[1],ll[2],ll[3]);
        }
        __syncthreads();
        #pragma unroll
        for(int kk2 = 0; kk2 < 32; kk2 += 8){
            uint32_t ah[2][4], al[2][4];
            #pragma unroll
            for(int mt = 0; mt < 2; mt++){
                int m0 = wm*32 + mt*16;
                ah[mt][0] = Ph[m0+g  ][kk2+t  ]; al[mt][0] = Pl[m0+g  ][kk2+t  ];
                ah[mt][1] = Ph[m0+g+8][kk2+t  ]; al[mt][1] = Pl[m0+g+8][kk2+t  ];
                ah[mt][2] = Ph[m0+g  ][kk2+t+4]; al[mt][2] = Pl[m0+g  ][kk2+t+4];
                ah[mt][3] = Ph[m0+g+8][kk2+t+4]; al[mt][3] = Pl[m0+g+8][kk2+t+4];
            }
            #pragma unroll
            for(int nt = 0; nt < 4; nt++){
                int n0 = wn*32 + nt*8 + g;
                uint32_t bh0 = Vh[kk2+t  ][n0], bl0 = Vl[kk2+t  ][n0];
                uint32_t bh1 = Vh[kk2+t+4][n0], bl1 = Vl[kk2+t+4][n0];
                #pragma unroll
                for(int mt = 0; mt < 2; mt++){
                    MMA3(acc[mt][nt], ah[mt], al[mt], bh0, bh1, bl0, bl1);
                }
            }
        }
        __syncthreads();
    }
    #pragma unroll
    for(int mt = 0; mt < 2; mt++){
        int row = ti*64 + wm*32 + mt*16 + g;
        #pragma unroll
        for(int nt = 0; nt < 4; nt++){
            int col = wn*32 + nt*8 + 2*t;
            float* op = o + (size_t)(b*TT + row)*DD + h*64 + col;
            *(float2*)op = make_float2(acc[mt][nt][0], acc[mt][nt][1]);
            *(float2*)(op + (size_t)8*DD) = make_float2(acc[mt][nt][2], acc[mt][nt][3]);
        }
    }
}

extern "C" void kernel_launch(void* const* d_in, const int* in_sizes, int n_in,
                              void* d_out, int out_size){
    const float* x         = (const float*)d_in[0];
    const float* summaries = (const float*)d_in[1];
    const float* ctx_w     = (const float*)d_in[2];
    const float* ctx_b     = (const float*)d_in[3];
    const float* base_adj  = (const float*)d_in[4];
    const float* warp_w    = (const float*)d_in[5];
    const float* warp_b    = (const float*)d_in[6];
    const float* gate_w    = (const float*)d_in[7];
    const float* gate_b    = (const float*)d_in[8];
    const float* g1_w      = (const float*)d_in[9];
    const float* g1_b      = (const float*)d_in[10];
    const float* g2_w      = (const float*)d_in[11];
    const float* g2_b      = (const float*)d_in[12];
    const float* ln1_g     = (const float*)d_in[13];
    const float* ln1_b     = (const float*)d_in[14];
    const float* wq        = (const float*)d_in[15];
    const float* bq        = (const float*)d_in[16];
    const float* wk        = (const float*)d_in[17];
    const float* bk        = (const float*)d_in[18];
    const float* wv        = (const float*)d_in[19];
    const float* bv        = (const float*)d_in[20];
    const float* wo        = (const float*)d_in[21];
    const float* bo        = (const float*)d_in[22];
    const float* ln2_g     = (const float*)d_in[23];
    const float* ln2_b     = (const float*)d_in[24];
    const float* ff1_w     = (const float*)d_in[25];
    const float* ff1_b     = (const float*)d_in[26];
    const float* ff2_w     = (const float*)d_in[27];
    const float* ff2_b     = (const float*)d_in[28];
    float* out = (float*)d_out;

    float *p_cur, *p_norm, *p_q, *p_k, *p_v, *p_o, *p_xo, *p_mid, *p_gate;
    cudaGetSymbolAddress((void**)&p_cur,  g_cur);
    cudaGetSymbolAddress((void**)&p_norm, g_norm);
    cudaGetSymbolAddress((void**)&p_q,    g_q);
    cudaGetSymbolAddress((void**)&p_k,    g_k);
    cudaGetSymbolAddress((void**)&p_v,    g_v);
    cudaGetSymbolAddress((void**)&p_o,    g_o);
    cudaGetSymbolAddress((void**)&p_xo,   g_xo);
    cudaGetSymbolAddress((void**)&p_mid,  g_mid);
    cudaGetSymbolAddress((void**)&p_gate, g_gate);

    const int CP_BLKS = BTD/4/256;

    k_copy_in<<<CP_BLKS,256>>>(x);

    // ---- router ----
    k_meanT_part<<<dim3(BB,32),256>>>(x);
    k_meanT_reduce<<<BB,256>>>();
    k_ctx<<<dim3(BB,32),128>>>(ctx_w, ctx_b);
    k_router<<<1,256>>>(summaries, base_adj, warp_w, warp_b, gate_w, gate_b,
                        out + BTD, out + BTD + 32, out + BTD + 32 + 256);

    // ---- 3 hops ----
    for(int hop = 0; hop < 3; hop++){
        k_meanT_part<<<dim3(BB,32),256>>>(p_cur);
        k_meanT_reduce<<<BB,256>>>();
        k_g1<<<BB,256>>>(g1_w, g1_b, hop);
        k_g2<<<1,256>>>(g2_w, g2_b, hop);
        k_ln<<<BT,256>>>(p_cur, ln1_g, ln1_b, hop, p_gate, p_norm);
        k_gemm_bf<<<dim3(8,32),256>>>(p_norm, wq, bq, nullptr, nullptr, p_q, DD, DD, hop, (long)DD*DD, DD, 0);
        k_gemm_bf<<<dim3(8,32),256>>>(p_norm, wk, bk, nullptr, nullptr, p_k, DD, DD, hop, (long)DD*DD, DD, 0);
        k_gemm_bf<<<dim3(8,32),256>>>(p_norm, wv, bv, nullptr, nullptr, p_v, DD, DD, hop, (long)DD*DD, DD, 0);
        k_scores_bf<<<dim3(16,16,BB*HH),128>>>(p_q, p_k);
        k_softmax<<<BB*HH*TT,128>>>();
        k_av_bf<<<dim3(16,BB*HH),128>>>(p_v, p_o);
        k_gemm_bf<<<dim3(8,32),256>>>(p_o, wo, bo, p_cur, p_gate, p_xo, DD, DD, hop, (long)DD*DD, DD, 0);
        k_ln<<<BT,256>>>(p_xo, ln2_g, ln2_b, hop, nullptr, p_norm);
        k_gemm_bf<<<dim3(32,32),256>>>(p_norm, ff1_w, ff1_b, nullptr, nullptr, p_mid, DFF, DD, hop, (long)DD*DFF, DFF, 1);
        k_gemm_bf<<<dim3(8,32),256>>>(p_mid, ff2_w, ff2_b, p_xo, nullptr, p_xo, DD, DFF, hop, (long)DFF*DD, DD, 0);
        k_mix<<<CP_BLKS,256>>>();
    }

    k_copy_out<<<CP_BLKS,256>>>(out);
}

// round 5
// speedup vs baseline: 2.4804x; 1.0579x over previous
#include <cuda_runtime.h>
#include <cuda_bf16.h>
#include <math.h>
#include <stdint.h>

#define BB 4
#define TT 1024
#define DD 1024
#define HH 16
#define DFF 4096
#define RR 8
#define BT (BB*TT)          // 4096
#define BTD (BB*TT*DD)      // 4194304
#define SZP (512*1024)      // packed words per D x D weight
#define SZF 2097152         // packed words per D x DFF weight

// ---------------- device scratch ----------------
__device__ float g_cur[BTD];
__device__ float g_xo[BTD];
__device__ float g_v[BTD];
__device__ float g_attn[(size_t)BB*HH*TT*TT];
__device__ __nv_bfloat16 g_ph[(size_t)BB*HH*TT*TT];
__device__ __nv_bfloat16 g_pl[(size_t)BB*HH*TT*TT];
__device__ uint32_t g_qh[BT*512], g_ql[BT*512];
__device__ uint32_t g_kh[BT*512], g_kl[BT*512];
__device__ uint32_t g_oh[BT*512], g_ol[BT*512];
__device__ uint32_t g_normh[BT*512], g_norml[BT*512];
__device__ uint32_t g_midh[BT*2048], g_midl[BT*2048];
__device__ uint32_t g_wph[4*SZP + 2*SZF], g_wpl[4*SZP + 2*SZF];
__device__ float g_part[BB*32*DD];
__device__ float g_ctxm[BB*DD];
__device__ float g_ctx[BB*DD];
__device__ float g_h1[BB*256];
__device__ float g_gate[BB];
__device__ float g_gm;
__device__ int   g_idx[3];

__device__ __forceinline__ float geluf(float x){
    return 0.5f*x*(1.0f+erff(x*0.7071067811865476f));
}
__device__ __forceinline__ void split2(float x, float y, uint32_t &hi, uint32_t &lo){
    __nv_bfloat16 xh = __float2bfloat16_rn(x);
    __nv_bfloat16 yh = __float2bfloat16_rn(y);
    __nv_bfloat162 h; h.x = xh; h.y = yh;
    __nv_bfloat162 l; l.x = __float2bfloat16_rn(x - __bfloat162float(xh));
    l.y = __float2bfloat16_rn(y - __bfloat162float(yh));
    hi = *(uint32_t*)&h; lo = *(uint32_t*)&l;
}
__device__ __forceinline__ void mma_bf16(float* c, uint32_t a0, uint32_t a1, uint32_t a2, uint32_t a3,
                                         uint32_t b0, uint32_t b1){
    asm volatile("mma.sync.aligned.m16n8k16.row.col.f32.bf16.bf16.f32 "
        "{%0,%1,%2,%3},{%4,%5,%6,%7},{%8,%9},{%0,%1,%2,%3};"
        : "+f"(c[0]), "+f"(c[1]), "+f"(c[2]), "+f"(c[3])
        : "r"(a0), "r"(a1), "r"(a2), "r"(a3), "r"(b0), "r"(b1));
}
#define MMA3(accp, AH, AL, BH0, BH1, BL0, BL1) \
    mma_bf16(accp, AH[0],AH[1],AH[2],AH[3], BH0, BH1); \
    mma_bf16(accp, AH[0],AH[1],AH[2],AH[3], BL0, BL1); \
    mma_bf16(accp, AL[0],AL[1],AL[2],AL[3], BH0, BH1);

__device__ __forceinline__ void cpa16(void* dst, const void* src){
    uint32_t d = (uint32_t)__cvta_generic_to_shared(dst);
    asm volatile("cp.async.cg.shared.global [%0], [%1], 16;" :: "r"(d), "l"(src));
}
#define CP_COMMIT() asm volatile("cp.async.commit_group;")

// ---------------- small kernels ----------------
__global__ void k_meanT_part(const float* __restrict__ in){
    int b = blockIdx.x, c = blockIdx.y;
    int t0 = c*32;
    for(int d = threadIdx.x; d < DD; d += 256){
        float s = 0.f;
        for(int t = t0; t < t0+32; t++) s += in[((size_t)(b*TT+t))*DD + d];
        g_part[(size_t)(b*32+c)*DD + d] = s;
    }
}
__global__ void k_meanT_reduce(){
    int b = blockIdx.x;
    for(int d = threadIdx.x; d < DD; d += 256){
        float s = 0.f;
        for(int c = 0; c < 32; c++) s += g_part[(size_t)(b*32+c)*DD + d];
        g_ctxm[b*DD + d] = s*(1.0f/TT);
    }
}
__global__ void k_ctx(const float* __restrict__ W, const float* __restrict__ bias){
    int b = blockIdx.x; int n0 = blockIdx.y*32;
    int lane = threadIdx.x & 31, q = threadIdx.x >> 5;
    const float* xv = &g_ctxm[b*DD];
    float s = 0.f;
    int k0 = q*256;
    for(int k = k0; k < k0+256; k++) s += xv[k]*W[(size_t)k*DD + n0 + lane];
    __shared__ float red[4][32];
    red[q][lane] = s; __syncthreads();
    if(q == 0)
        g_ctx[b*DD + n0 + lane] = red[0][lane]+red[1][lane]+red[2][lane]+red[3][lane] + bias[n0+lane];
}
__global__ void k_router(const float* __restrict__ summaries, const float* __restrict__ base_adj,
                         const float* __restrict__ warp_w, const float* __restrict__ warp_b,
                         const float* __restrict__ gate_w, const float* __restrict__ gate_b,
                         float* __restrict__ out_gs, float* __restrict__ out_adj,
                         float* __restrict__ out_mh){
    __shared__ float s_warp[BB][64];
    __shared__ float s_dir[BB][RR];
    __shared__ float s_gl[BB][RR];
    __shared__ float s_gs[BB][RR];
    int tid = threadIdx.x;
    {   int b = tid/64, c = tid%64;
        const float* xv = &g_ctx[b*DD];
        float s = warp_b[c];
        for(int k = 0; k < DD; k++) s += xv[k]*warp_w[(size_t)k*64 + c];
        s_warp[b][c] = s*0.1f;
    }
    if(tid < 32){
        int b = tid/8, r = tid%8;
        const float* xv = &g_ctx[b*DD];
        float s = 0.f;
        for(int k = 0; k < DD; k++) s += xv[k]*summaries[r*DD + k];
        s_dir[b][r] = s;
    } else if(tid < 64){
        int t = tid-32; int b = t/8, r = t%8;
        const float* xv = &g_ctx[b*DD];
        float s = gate_b[r];
        for(int k = 0; k < DD; k++) s += xv[k]*gate_w[k*RR + r];
        s_gl[b][r] = s;
    }
    __syncthreads();
    if(tid < 32){
        int b = tid/8, i = tid%8;
        float v[8]; float mx = -1e30f;
        for(int j = 0; j < 8; j++){ v[j] = base_adj[i*8+j] + s_warp[b][i*8+j]; mx = fmaxf(mx, v[j]); }
        float sum = 0.f;
        for(int j = 0; j < 8; j++){ v[j] = expf(v[j]-mx); sum += v[j]; }
        float inv = 1.0f/sum;
        float boost = 0.f;
        for(int j = 0; j < 8; j++){
            float a = v[j]*inv;
            out_adj[(b*8+i)*8 + j] = a;
            boost += a*s_dir[b][j];
        }
        float gs = 1.0f/(1.0f+expf(-(s_gl[b][i]+boost)*0.5f));
        out_gs[b*8+i] = gs;
        s_gs[b][i] = gs;
    }
    __syncthreads();
    if(tid == 0){
        float m[RR];
        for(int r = 0; r < 8; r++) m[r] = 0.25f*(s_gs[0][r]+s_gs[1][r]+s_gs[2][r]+s_gs[3][r]);
        for(int h = 0; h < 3; h++){
            int best = 0; float bv = -1e30f;
            for(int r = 0; r < 8; r++) if(m[r] > bv){ bv = m[r]; best = r; }
            g_idx[h] = best; m[best] = -1e30f;
        }
        out_mh[0] = 3.0f;
    }
}
__global__ void k_g1(const float* __restrict__ g1_w, const float* __restrict__ g1_b, int hop){
    int room = g_idx[hop];
    int b = blockIdx.x, n = threadIdx.x;
    const float* W = g1_w + (size_t)room*DD*256;
    const float* xv = &g_ctxm[b*DD];
    float s = g1_b[room*256 + n];
    for(int k = 0; k < DD; k++) s += xv[k]*W[(size_t)k*256 + n];
    g_h1[b*256 + n] = geluf(s);
}
__global__ void k_g2(const float* __restrict__ g2_w, const float* __restrict__ g2_b, int hop){
    int room = g_idx[hop];
    __shared__ float red[256];
    int tid = threadIdx.x;
    int b = tid/64, lane = tid%64;
    const float* W = g2_w + room*256;
    float s = 0.f;
    for(int k = lane; k < 256; k += 64) s += g_h1[b*256 + k]*W[k];
    red[tid] = s; __syncthreads();
    for(int off = 32; off >= 1; off >>= 1){
        if(lane < off) red[tid] += red[tid+off];
        __syncthreads();
    }
    if(lane == 0){
        float gate = 1.0f/(1.0f+expf(-(red[tid]+g2_b[room])));
        g_gate[b] = gate;
    }
    __syncthreads();
    if(tid == 0) g_gm = 0.25f*(g_gate[0]+g_gate[1]+g_gate[2]+g_gate[3]);
}

// weight pre-pack: vertical k-pairs, split hi/lo
__global__ void k_packw(const float* __restrict__ Wb, uint32_t* __restrict__ oh, uint32_t* __restrict__ ol,
                        int N, int halfK, int hop, long wstr){
    int room = g_idx[hop];
    const float* W = Wb + (size_t)room*wstr;
    int i = blockIdx.x*256 + threadIdx.x;
    int k2 = i / N, n = i % N;
    float a = W[(size_t)(2*k2)*N + n];
    float b = W[(size_t)(2*k2+1)*N + n];
    uint32_t hh, ll; split2(a, b, hh, ll);
    oh[i] = hh; ol[i] = ll;
}

// layernorm -> split bf16 planes (optional per-batch gate prescale)
__global__ void __launch_bounds__(256) k_ln2(const float* __restrict__ in,
                     const float* __restrict__ gb, const float* __restrict__ bb,
                     int hop, const float* __restrict__ gate,
                     uint32_t* __restrict__ oh, uint32_t* __restrict__ ol){
    int row = blockIdx.x; int b = row >> 10;
    int room = g_idx[hop];
    float sc = gate ? gate[b] : 1.0f;
    float4 v = ((const float4*)(in + (size_t)row*DD))[threadIdx.x];
    v.x *= sc; v.y *= sc; v.z *= sc; v.w *= sc;
    __shared__ float rs[256], rq[256];
    rs[threadIdx.x] = v.x+v.y+v.z+v.w;
    rq[threadIdx.x] = v.x*v.x+v.y*v.y+v.z*v.z+v.w*v.w;
    __syncthreads();
    for(int off = 128; off >= 1; off >>= 1){
        if(threadIdx.x < off){ rs[threadIdx.x] += rs[threadIdx.x+off]; rq[threadIdx.x] += rq[threadIdx.x+off]; }
        __syncthreads();
    }
    float mean = rs[0]*(1.0f/DD);
    float var  = rq[0]*(1.0f/DD) - mean*mean;
    float inv  = rsqrtf(var + 1e-5f);
    float4 g4 = ((const float4*)(gb + (size_t)room*DD))[threadIdx.x];
    float4 b4 = ((const float4*)(bb + (size_t)room*DD))[threadIdx.x];
    float o0 = (v.x-mean)*inv*g4.x + b4.x;
    float o1 = (v.y-mean)*inv*g4.y + b4.y;
    float o2 = (v.z-mean)*inv*g4.z + b4.z;
    float o3 = (v.w-mean)*inv*g4.w + b4.w;
    uint32_t h0,l0,h1,l1;
    split2(o0,o1,h0,l0); split2(o2,o3,h1,l1);
    size_t w = (size_t)row*512 + threadIdx.x*2;
    *(uint2*)&oh[w] = make_uint2(h0,h1);
    *(uint2*)&ol[w] = make_uint2(l0,l1);
}

// ---------------- bf16x3 GEMM, pre-split operands, cp.async double buffer ----------------
// mode 0: C=f32 (+ res*rscale); mode 1: split planes Ch/Cl (opt gelu); mode 2: fused mix
__global__ void __launch_bounds__(256,2) k_gemm3(
        const uint32_t* __restrict__ Ah, const uint32_t* __restrict__ Al,
        const uint32_t* __restrict__ Wh, const uint32_t* __restrict__ Wl,
        const float* __restrict__ bbase, long bstr, int hop,
        const float* __restrict__ res, const float* __restrict__ rscale,
        const float* __restrict__ curin,
        float* __restrict__ C, uint32_t* __restrict__ Ch, uint32_t* __restrict__ Cl,
        int N, int K, int act, int mode){
    int room = g_idx[hop];
    const float* bias = bbase + (size_t)room*bstr;
    __shared__ uint32_t sAh[2][128][12], sAl[2][128][12];
    __shared__ uint32_t sBh[2][8][136],  sBl[2][8][136];
    int tid = threadIdx.x;
    int bm = blockIdx.y, bn = blockIdx.x;
    int warp = tid>>5, lane = tid&31;
    int g = lane>>2, t = lane&3;
    int wm = warp>>1, wn = warp&1;
    int halfK = K >> 1;

    int ar = tid>>1, ac = (tid&1)*4;      // A: 128 rows x 2 chunks of 4 words
    int bk = tid>>5, bc = (tid&31)*4;     // B: 8 rows x 32 chunks
    const uint32_t* Ah_src = Ah + (size_t)(bm*128 + ar)*halfK + ac;
    const uint32_t* Al_src = Al + (size_t)(bm*128 + ar)*halfK + ac;
    const uint32_t* Wh_src = Wh + (size_t)bk*N + bn*128 + bc;
    const uint32_t* Wl_src = Wl + (size_t)bk*N + bn*128 + bc;

    int nC = K >> 4;
    // prologue: stage chunk 0 into buf 0
    cpa16(&sAh[0][ar][ac], Ah_src);
    cpa16(&sAl[0][ar][ac], Al_src);
    cpa16(&sBh[0][bk][bc], Wh_src);
    cpa16(&sBl[0][bk][bc], Wl_src);
    CP_COMMIT();

    float acc[2][8][4] = {};
    for(int c = 0; c < nC; c++){
        if(c+1 < nC){
            int k2o = (c+1)*8;
            int nb = (c+1)&1;
            cpa16(&sAh[nb][ar][ac], Ah_src + k2o);
            cpa16(&sAl[nb][ar][ac], Al_src + k2o);
            cpa16(&sBh[nb][bk][bc], Wh_src + (size_t)k2o*N);
            cpa16(&sBl[nb][bk][bc], Wl_src + (size_t)k2o*N);
            CP_COMMIT();
            asm volatile("cp.async.wait_group 1;");
        } else {
            asm volatile("cp.async.wait_group 0;");
        }
        __syncthreads();
        int cb = c&1;
        uint32_t ah[2][4], al[2][4];
        #pragma unroll
        for(int mt = 0; mt < 2; mt++){
            int m0 = wm*32 + mt*16;
            ah[mt][0] = sAh[cb][m0+g  ][t  ]; al[mt][0] = sAl[cb][m0+g  ][t  ];
            ah[mt][1] = sAh[cb][m0+g+8][t  ]; al[mt][1] = sAl[cb][m0+g+8][t  ];
            ah[mt][2] = sAh[cb][m0+g  ][t+4]; al[mt][2] = sAl[cb][m0+g  ][t+4];
            ah[mt][3] = sAh[cb][m0+g+8][t+4]; al[mt][3] = sAl[cb][m0+g+8][t+4];
        }
        #pragma unroll
        for(int nt = 0; nt < 8; nt++){
            int n0 = wn*64 + nt*8 + g;
            uint32_t bh0 = sBh[cb][t  ][n0], bl0 = sBl[cb][t  ][n0];
            uint32_t bh1 = sBh[cb][t+4][n0], bl1 = sBl[cb][t+4][n0];
            #pragma unroll
            for(int mt = 0; mt < 2; mt++){
                MMA3(acc[mt][nt], ah[mt], al[mt], bh0, bh1, bl0, bl1);
            }
        }
        __syncthreads();
    }

    float gm = (mode == 2) ? g_gm : 0.f;
    #pragma unroll
    for(int mt = 0; mt < 2; mt++){
        int row = bm*128 + wm*32 + mt*16 + g;
        #pragma unroll
        for(int nt = 0; nt < 8; nt++){
            int col = bn*128 + wn*64 + nt*8 + 2*t;
            float2 bi = *(const float2*)&bias[col];
            float v0 = acc[mt][nt][0] + bi.x;
            float v1 = acc[mt][nt][1] + bi.y;
            float v2 = acc[mt][nt][2] + bi.x;
            float v3 = acc[mt][nt][3] + bi.y;
            if(act == 1){
                v0 = geluf(v0); v1 = geluf(v1); v2 = geluf(v2); v3 = geluf(v3);
            }
            size_t i0 = (size_t)row*N + col, i1 = (size_t)(row+8)*N + col;
            if(mode == 0){
                if(res){
                    float sc = rscale ? rscale[row>>10] : 1.0f;
                    float2 r0 = *(const float2*)&res[i0];
                    float2 r1 = *(const float2*)&res[i1];
                    v0 += r0.x*sc; v1 += r0.y*sc; v2 += r1.x*sc; v3 += r1.y*sc;
                }
                *(float2*)&C[i0] = make_float2(v0, v1);
                *(float2*)&C[i1] = make_float2(v2, v3);
            } else if(mode == 1){
                uint32_t hh, ll;
                size_t w0 = (size_t)row*(N>>1) + (col>>1);
                size_t w1 = (size_t)(row+8)*(N>>1) + (col>>1);
                split2(v0, v1, hh, ll); Ch[w0] = hh; Cl[w0] = ll;
                split2(v2, v3, hh, ll); Ch[w1] = hh; Cl[w1] = ll;
            } else {
                float2 r0 = *(const float2*)&res[i0];
                float2 r1 = *(const float2*)&res[i1];
                float2 c0 = *(const float2*)&curin[i0];
                float2 c1 = *(const float2*)&curin[i1];
                float x0 = r0.x + v0, x1 = r0.y + v1, x2 = r1.x + v2, x3 = r1.y + v3;
                *(float2*)&C[i0] = make_float2(c0.x + gm*(x0-c0.x), c0.y + gm*(x1-c0.y));
                *(float2*)&C[i1] = make_float2(c1.x + gm*(x2-c1.x), c1.y + gm*(x3-c1.y));
            }
        }
    }
}

// ---------------- attention scores (pre-split planes) ----------------
__global__ void __launch_bounds__(128) k_scores2(){
    int ti = blockIdx.x, tj = blockIdx.y;
    if(tj > ti) return;
    int bh = blockIdx.z; int b = bh>>4, h = bh&15;
    __shared__ uint32_t Qh[64][36], Ql[64][36];
    __shared__ uint32_t Kh[64][36], Kl[64][36];
    int tid = threadIdx.x;
    int warp = tid>>5, lane = tid&31;
    int g = lane>>2, t = lane&3;
    int wm = warp>>1, wn = warp&1;

    #pragma unroll
    for(int i = 0; i < 4; i++){
        int idx = tid + 128*i;          // 0..511
        int r = idx>>3, c = (idx&7)*4;
        size_t qoff = ((size_t)(b*TT + ti*64 + r))*512 + h*32 + c;
        size_t koff = ((size_t)(b*TT + tj*64 + r))*512 + h*32 + c;
        *(uint4*)&Qh[r][c] = *(const uint4*)(g_qh + qoff);
        *(uint4*)&Ql[r][c] = *(const uint4*)(g_ql + qoff);
        *(uint4*)&Kh[r][c] = *(const uint4*)(g_kh + koff);
        *(uint4*)&Kl[r][c] = *(const uint4*)(g_kl + koff);
    }
    __syncthreads();

    float acc[2][4][4] = {};
    #pragma unroll
    for(int kk2 = 0; kk2 < 32; kk2 += 8){
        uint32_t ah[2][4], al[2][4];
        #pragma unroll
        for(int mt = 0; mt < 2; mt++){
            int m0 = wm*32 + mt*16;
            ah[mt][0] = Qh[m0+g  ][kk2+t  ]; al[mt][0] = Ql[m0+g  ][kk2+t  ];
            ah[mt][1] = Qh[m0+g+8][kk2+t  ]; al[mt][1] = Ql[m0+g+8][kk2+t  ];
            ah[mt][2] = Qh[m0+g  ][kk2+t+4]; al[mt][2] = Ql[m0+g  ][kk2+t+4];
            ah[mt][3] = Qh[m0+g+8][kk2+t+4]; al[mt][3] = Ql[m0+g+8][kk2+t+4];
        }
        #pragma unroll
        for(int nt = 0; nt < 4; nt++){
            int n0 = wn*32 + nt*8 + g;
            uint32_t bh0 = Kh[n0][kk2+t  ], bl0 = Kl[n0][kk2+t  ];
            uint32_t bh1 = Kh[n0][kk2+t+4], bl1 = Kl[n0][kk2+t+4];
            #pragma unroll
            for(int mt = 0; mt < 2; mt++){
                MMA3(acc[mt][nt], ah[mt], al[mt], bh0, bh1, bl0, bl1);
            }
        }
    }
    #pragma unroll
    for(int mt = 0; mt < 2; mt++){
        int row = ti*64 + wm*32 + mt*16 + g;
        #pragma unroll
        for(int nt = 0; nt < 4; nt++){
            int col = tj*64 + wn*32 + nt*8 + 2*t;
            float* sp = g_attn + ((size_t)bh*TT + row)*TT + col;
            *(float2*)sp = make_float2(acc[mt][nt][0]*0.125f, acc[mt][nt][1]*0.125f);
            *(float2*)(sp + (size_t)8*TT) = make_float2(acc[mt][nt][2]*0.125f, acc[mt][nt][3]*0.125f);
        }
    }
}

// softmax: f32 scores -> split bf16 probs; zero fill only within diagonal tile
__global__ void __launch_bounds__(128) k_softmax2(){
    int row = blockIdx.x;                  // bh*T + i
    int i = row & (TT-1);
    const float* p = g_attn + (size_t)row*TT;
    __nv_bfloat16* ph = g_ph + (size_t)row*TT;
    __nv_bfloat16* pl = g_pl + (size_t)row*TT;
    int len = i+1, tid = threadIdx.x;
    int tend = ((i>>6)+1)<<6;              // end of diagonal 64-tile
    __shared__ float red[128];
    float mx = -1e30f;
    for(int j = tid; j < len; j += 128) mx = fmaxf(mx, p[j]);
    red[tid] = mx; __syncthreads();
    for(int off = 64; off >= 1; off >>= 1){
        if(tid < off) red[tid] = fmaxf(red[tid], red[tid+off]);
        __syncthreads();
    }
    mx = red[0]; __syncthreads();
    float s = 0.f;
    for(int j = tid; j < len; j += 128) s += expf(p[j]-mx);
    red[tid] = s; __syncthreads();
    for(int off = 64; off >= 1; off >>= 1){
        if(tid < off) red[tid] += red[tid+off];
        __syncthreads();
    }
    float inv = 1.0f/red[0];
    for(int j = tid; j < len; j += 128){
        float e = expf(p[j]-mx)*inv;
        __nv_bfloat16 hb = __float2bfloat16_rn(e);
        ph[j] = hb;
        pl[j] = __float2bfloat16_rn(e - __bfloat162float(hb));
    }
    __nv_bfloat16 z = __float2bfloat16_rn(0.f);
    for(int j = len + tid; j < tend; j += 128){ ph[j] = z; pl[j] = z; }
}

// o = P @ V per (bh); P from split planes, V f32 split in staging; out split planes
__global__ void __launch_bounds__(128) k_av2(const float* __restrict__ v){
    int ti = blockIdx.x; int bh = blockIdx.y;
    int b = bh>>4, h = bh&15;
    __shared__ uint32_t Ph[64][36], Pl[64][36];
    __shared__ uint32_t Vh[32][72], Vl[32][72];
    int tid = threadIdx.x;
    int warp = tid>>5, lane = tid&31;
    int g = lane>>2, t = lane&3;
    int wm = warp>>1, wn = warp&1;
    int vk2 = tid>>4, vn4 = tid&15;

    const uint32_t* phw = (const uint32_t*)g_ph;
    const uint32_t* plw = (const uint32_t*)g_pl;

    float acc[2][4][4] = {};
    for(int kt = 0; kt <= ti; kt++){
        #pragma unroll
        for(int i = 0; i < 4; i++){
            int idx = tid + 128*i;
            int r = idx>>3, c = (idx&7)*4;
            size_t poff = ((size_t)bh*TT + ti*64 + r)*512 + kt*32 + c;
            *(uint4*)&Ph[r][c] = *(const uint4*)(phw + poff);
            *(uint4*)&Pl[r][c] = *(const uint4*)(plw + poff);
        }
        #pragma unroll
        for(int i = 0; i < 4; i++){
            int k2 = vk2 + 8*i;
            const float* v0 = v + (size_t)(b*TT + kt*64 + 2*k2  )*DD + h*64 + vn4*4;
            const float* v1 = v + (size_t)(b*TT + kt*64 + 2*k2+1)*DD + h*64 + vn4*4;
            float4 a4 = *(const float4*)v0;
            float4 b4 = *(const float4*)v1;
            const float* r0 = (const float*)&a4;
            const float* r1 = (const float*)&b4;
            uint32_t hh[4], ll[4];
            #pragma unroll
            for(int j = 0; j < 4; j++) split2(r0[j], r1[j], hh[j], ll[j]);
            *(uint4*)&Vh[k2][vn4*4] = make_uint4(hh[0],hh[1],hh[2],hh[3]);
            *(uint4*)&Vl[k2][vn4*4] = make_uint4(ll[0],ll[1],ll[2],ll[3]);
        }
        __syncthreads();
        #pragma unroll
        for(int kk2 = 0; kk2 < 32; kk2 += 8){
            uint32_t ah[2][4], al[2][4];
            #pragma unroll
            for(int mt = 0; mt < 2; mt++){
                int m0 = wm*32 + mt*16;
                ah[mt][0] = Ph[m0+g  ][kk2+t  ]; al[mt][0] = Pl[m0+g  ][kk2+t  ];
                ah[mt][1] = Ph[m0+g+8][kk2+t  ]; al[mt][1] = Pl[m0+g+8][kk2+t  ];
                ah[mt][2] = Ph[m0+g  ][kk2+t+4]; al[mt][2] = Pl[m0+g  ][kk2+t+4];
                ah[mt][3] = Ph[m0+g+8][kk2+t+4]; al[mt][3] = Pl[m0+g+8][kk2+t+4];
            }
            #pragma unroll
            for(int nt = 0; nt < 4; nt++){
                int n0 = wn*32 + nt*8 + g;
                uint32_t bh0 = Vh[kk2+t  ][n0], bl0 = Vl[kk2+t  ][n0];
                uint32_t bh1 = Vh[kk2+t+4][n0], bl1 = Vl[kk2+t+4][n0];
                #pragma unroll
                for(int mt = 0; mt < 2; mt++){
                    MMA3(acc[mt][nt], ah[mt], al[mt], bh0, bh1, bl0, bl1);
                }
            }
        }
        __syncthreads();
    }
    #pragma unroll
    for(int mt = 0; mt < 2; mt++){
        int row = ti*64 + wm*32 + mt*16 + g;
        #pragma unroll
        for(int nt = 0; nt < 4; nt++){
            int col = wn*32 + nt*8 + 2*t;
            size_t w0 = ((size_t)(b*TT + row))*512 + (h*64 + col)/2;
            size_t w1 = ((size_t)(b*TT + row + 8))*512 + (h*64 + col)/2;
            uint32_t hh, ll;
            split2(acc[mt][nt][0], acc[mt][nt][1], hh, ll);
            g_oh[w0] = hh; g_ol[w0] = ll;
            split2(acc[mt][nt][2], acc[mt][nt][3], hh, ll);
            g_oh[w1] = hh; g_ol[w1] = ll;
        }
    }
}

extern "C" void kernel_launch(void* const* d_in, const int* in_sizes, int n_in,
                              void* d_out, int out_size){
    const float* x         = (const float*)d_in[0];
    const float* summaries = (const float*)d_in[1];
    const float* ctx_w     = (const float*)d_in[2];
    const float* ctx_b     = (const float*)d_in[3];
    const float* base_adj  = (const float*)d_in[4];
    const float* warp_w    = (const float*)d_in[5];
    const float* warp_b    = (const float*)d_in[6];
    const float* gate_w    = (const float*)d_in[7];
    const float* gate_b    = (const float*)d_in[8];
    const float* g1_w      = (const float*)d_in[9];
    const float* g1_b      = (const float*)d_in[10];
    const float* g2_w      = (const float*)d_in[11];
    const float* g2_b      = (const float*)d_in[12];
    const float* ln1_g     = (const float*)d_in[13];
    const float* ln1_b     = (const float*)d_in[14];
    const float* wq        = (const float*)d_in[15];
    const float* bq        = (const float*)d_in[16];
    const float* wk        = (const float*)d_in[17];
    const float* bk        = (const float*)d_in[18];
    const float* wv        = (const float*)d_in[19];
    const float* bv        = (const float*)d_in[20];
    const float* wo        = (const float*)d_in[21];
    const float* bo        = (const float*)d_in[22];
    const float* ln2_g     = (const float*)d_in[23];
    const float* ln2_b     = (const float*)d_in[24];
    const float* ff1_w     = (const float*)d_in[25];
    const float* ff1_b     = (const float*)d_in[26];
    const float* ff2_w     = (const float*)d_in[27];
    const float* ff2_b     = (const float*)d_in[28];
    float* out = (float*)d_out;

    float *p_cur, *p_xo, *p_v, *p_gate;
    uint32_t *p_qh,*p_ql,*p_kh,*p_kl,*p_oh,*p_ol,*p_nh,*p_nl,*p_mh,*p_ml,*p_wph,*p_wpl;
    cudaGetSymbolAddress((void**)&p_cur,  g_cur);
    cudaGetSymbolAddress((void**)&p_xo,   g_xo);
    cudaGetSymbolAddress((void**)&p_v,    g_v);
    cudaGetSymbolAddress((void**)&p_gate, g_gate);
    cudaGetSymbolAddress((void**)&p_qh, g_qh);  cudaGetSymbolAddress((void**)&p_ql, g_ql);
    cudaGetSymbolAddress((void**)&p_kh, g_kh);  cudaGetSymbolAddress((void**)&p_kl, g_kl);
    cudaGetSymbolAddress((void**)&p_oh, g_oh);  cudaGetSymbolAddress((void**)&p_ol, g_ol);
    cudaGetSymbolAddress((void**)&p_nh, g_normh); cudaGetSymbolAddress((void**)&p_nl, g_norml);
    cudaGetSymbolAddress((void**)&p_mh, g_midh); cudaGetSymbolAddress((void**)&p_ml, g_midl);
    cudaGetSymbolAddress((void**)&p_wph, g_wph); cudaGetSymbolAddress((void**)&p_wpl, g_wpl);

    // ---- router ----
    k_meanT_part<<<dim3(BB,32),256>>>(x);
    k_meanT_reduce<<<BB,256>>>();
    k_ctx<<<dim3(BB,32),128>>>(ctx_w, ctx_b);
    k_router<<<1,256>>>(summaries, base_adj, warp_w, warp_b, gate_w, gate_b,
                        out + BTD, out + BTD + 32, out + BTD + 32 + 256);

    // ---- 3 hops ----
    for(int hop = 0; hop < 3; hop++){
        const float* cin = (hop == 0) ? x : p_cur;
        float* cout = (hop == 2) ? out : p_cur;

        // pack this hop's weights
        k_packw<<<SZP/256,256>>>(wq,  p_wph+0*SZP, p_wpl+0*SZP, DD,  512,  hop, (long)DD*DD);
        k_packw<<<SZP/256,256>>>(wk,  p_wph+1*SZP, p_wpl+1*SZP, DD,  512,  hop, (long)DD*DD);
        k_packw<<<SZP/256,256>>>(wv,  p_wph+2*SZP, p_wpl+2*SZP, DD,  512,  hop, (long)DD*DD);
        k_packw<<<SZP/256,256>>>(wo,  p_wph+3*SZP, p_wpl+3*SZP, DD,  512,  hop, (long)DD*DD);
        k_packw<<<SZF/256,256>>>(ff1_w, p_wph+4*SZP,     p_wpl+4*SZP,     DFF, 512,  hop, (long)DD*DFF);
        k_packw<<<SZF/256,256>>>(ff2_w, p_wph+4*SZP+SZF, p_wpl+4*SZP+SZF, DD,  2048, hop, (long)DFF*DD);

        if(hop > 0){
            k_meanT_part<<<dim3(BB,32),256>>>(cin);
            k_meanT_reduce<<<BB,256>>>();
        }
        k_g1<<<BB,256>>>(g1_w, g1_b, hop);
        k_g2<<<1,256>>>(g2_w, g2_b, hop);
        k_ln2<<<BT,256>>>(cin, ln1_g, ln1_b, hop, p_gate, p_nh, p_nl);
        // q,k,v
        k_gemm3<<<dim3(8,32),256>>>(p_nh,p_nl, p_wph+0*SZP,p_wpl+0*SZP, bq, DD, hop,
                                    nullptr,nullptr,nullptr, nullptr, p_qh,p_ql, DD, DD, 0, 1);
        k_gemm3<<<dim3(8,32),256>>>(p_nh,p_nl, p_wph+1*SZP,p_wpl+1*SZP, bk, DD, hop,
                                    nullptr,nullptr,nullptr, nullptr, p_kh,p_kl, DD, DD, 0, 1);
        k_gemm3<<<dim3(8,32),256>>>(p_nh,p_nl, p_wph+2*SZP,p_wpl+2*SZP, bv, DD, hop,
                                    nullptr,nullptr,nullptr, p_v, nullptr,nullptr, DD, DD, 0, 0);
        // attention
        k_scores2<<<dim3(16,16,BB*HH),128>>>();
        k_softmax2<<<BB*HH*TT,128>>>();
        k_av2<<<dim3(16,BB*HH),128>>>(p_v);
        // xo = cur*gate + o@wo + bo
        k_gemm3<<<dim3(8,32),256>>>(p_oh,p_ol, p_wph+3*SZP,p_wpl+3*SZP, bo, DD, hop,
                                    cin, p_gate, nullptr, p_xo, nullptr,nullptr, DD, DD, 0, 0);
        // ffn
        k_ln2<<<BT,256>>>(p_xo, ln2_g, ln2_b, hop, nullptr, p_nh, p_nl);
        k_gemm3<<<dim3(32,32),256>>>(p_nh,p_nl, p_wph+4*SZP,p_wpl+4*SZP, ff1_b, DFF, hop,
                                    nullptr,nullptr,nullptr, nullptr, p_mh,p_ml, DFF, DD, 1, 1);
        // ff2 + fused mix: cout = cin + gm*((xo + mid@ff2 + b) - cin)
        k_gemm3<<<dim3(8,32),256>>>(p_mh,p_ml, p_wph+4*SZP+SZF,p_wpl+4*SZP+SZF, ff2_b, DD, hop,
                                    p_xo, nullptr, cin, cout, nullptr,nullptr, DD, DFF, 0, 2);
    }
}

// round 6
// speedup vs baseline: 2.5591x; 1.0317x over previous
#include <cuda_runtime.h>
#include <cuda_bf16.h>
#include <math.h>
#include <stdint.h>

#define BB 4
#define TT 1024
#define DD 1024
#define HH 16
#define DFF 4096
#define RR 8
#define BT (BB*TT)
#define BTD (BB*TT*DD)
#define SZP (512*1024)
#define SZF 2097152

// ---------------- device scratch ----------------
__device__ float g_cur[BTD];
__device__ float g_xo[BTD];
__device__ float g_v[BTD];
__device__ float g_attn[(size_t)BB*HH*TT*TT];
__device__ __nv_bfloat16 g_ph[(size_t)BB*HH*TT*TT];
__device__ __nv_bfloat16 g_pl[(size_t)BB*HH*TT*TT];
__device__ uint32_t g_qh[BT*512], g_ql[BT*512];
__device__ uint32_t g_kh[BT*512], g_kl[BT*512];
__device__ uint32_t g_oh[BT*512], g_ol[BT*512];
__device__ uint32_t g_normh[BT*512], g_norml[BT*512];
__device__ uint32_t g_midh[BT*2048], g_midl[BT*2048];
__device__ uint32_t g_wph[4*SZP + 2*SZF], g_wpl[4*SZP + 2*SZF];
__device__ float g_part[BB*32*DD];
__device__ float g_ctxm[BB*DD];
__device__ float g_ctx[BB*DD];
__device__ float g_rt[BB*80];
__device__ float g_h1[BB*256];
__device__ float g_gate[BB];
__device__ float g_gm;
__device__ int   g_idx[3];

__device__ __forceinline__ float geluf(float x){
    return 0.5f*x*(1.0f+erff(x*0.7071067811865476f));
}
__device__ __forceinline__ void split2(float x, float y, uint32_t &hi, uint32_t &lo){
    __nv_bfloat16 xh = __float2bfloat16_rn(x);
    __nv_bfloat16 yh = __float2bfloat16_rn(y);
    __nv_bfloat162 h; h.x = xh; h.y = yh;
    __nv_bfloat162 l; l.x = __float2bfloat16_rn(x - __bfloat162float(xh));
    l.y = __float2bfloat16_rn(y - __bfloat162float(yh));
    hi = *(uint32_t*)&h; lo = *(uint32_t*)&l;
}
__device__ __forceinline__ void mma_bf16(float* c, uint32_t a0, uint32_t a1, uint32_t a2, uint32_t a3,
                                         uint32_t b0, uint32_t b1){
    asm volatile("mma.sync.aligned.m16n8k16.row.col.f32.bf16.bf16.f32 "
        "{%0,%1,%2,%3},{%4,%5,%6,%7},{%8,%9},{%0,%1,%2,%3};"
        : "+f"(c[0]), "+f"(c[1]), "+f"(c[2]), "+f"(c[3])
        : "r"(a0), "r"(a1), "r"(a2), "r"(a3), "r"(b0), "r"(b1));
}
#define MMA3(accp, AH, AL, BH0, BH1, BL0, BL1) \
    mma_bf16(accp, AH[0],AH[1],AH[2],AH[3], BH0, BH1); \
    mma_bf16(accp, AH[0],AH[1],AH[2],AH[3], BL0, BL1); \
    mma_bf16(accp, AL[0],AL[1],AL[2],AL[3], BH0, BH1);

__device__ __forceinline__ void cpa16(void* dst, const void* src){
    uint32_t d = (uint32_t)__cvta_generic_to_shared(dst);
    asm volatile("cp.async.cg.shared.global [%0], [%1], 16;" :: "r"(d), "l"(src));
}
#define CP_COMMIT() asm volatile("cp.async.commit_group;")

// ---------------- small kernels ----------------
__global__ void k_meanT_part(const float* __restrict__ in){
    int b = blockIdx.x, c = blockIdx.y;
    int t0 = c*32;
    for(int d = threadIdx.x; d < DD; d += 256){
        float s = 0.f;
        for(int t = t0; t < t0+32; t++) s += in[((size_t)(b*TT+t))*DD + d];
        g_part[(size_t)(b*32+c)*DD + d] = s;
    }
}
__global__ void k_meanT_reduce(){
    int b = blockIdx.x;
    for(int d = threadIdx.x; d < DD; d += 256){
        float s = 0.f;
        for(int c = 0; c < 32; c++) s += g_part[(size_t)(b*32+c)*DD + d];
        g_ctxm[b*DD + d] = s*(1.0f/TT);
    }
}
__global__ void k_ctx(const float* __restrict__ W, const float* __restrict__ bias){
    int b = blockIdx.x; int n0 = blockIdx.y*32;
    int lane = threadIdx.x & 31, q = threadIdx.x >> 5;
    const float* xv = &g_ctxm[b*DD];
    float s = 0.f;
    int k0 = q*256;
    for(int k = k0; k < k0+256; k++) s += xv[k]*W[(size_t)k*DD + n0 + lane];
    __shared__ float red[4][32];
    red[q][lane] = s; __syncthreads();
    if(q == 0)
        g_ctx[b*DD + n0 + lane] = red[0][lane]+red[1][lane]+red[2][lane]+red[3][lane] + bias[n0+lane];
}

// router stage 1: 80 dots per batch, parallel. o<64: warp_w col; o<72: summaries row; else gate_w col
__global__ void __launch_bounds__(128) k_route1(const float* __restrict__ warp_w,
        const float* __restrict__ summaries, const float* __restrict__ gate_w){
    int b = blockIdx.x, o = blockIdx.y;
    int tid = threadIdx.x;
    const float* xv = &g_ctx[b*DD];
    float s = 0.f;
    if(o < 64){
        for(int k = tid; k < DD; k += 128) s += xv[k]*warp_w[(size_t)k*64 + o];
    } else if(o < 72){
        const float* sr = summaries + (size_t)(o-64)*DD;
        for(int k = tid; k < DD; k += 128) s += xv[k]*sr[k];
    } else {
        for(int k = tid; k < DD; k += 128) s += xv[k]*gate_w[k*RR + (o-72)];
    }
    __shared__ float red[128];
    red[tid] = s; __syncthreads();
    for(int off = 64; off >= 1; off >>= 1){
        if(tid < off) red[tid] += red[tid+off];
        __syncthreads();
    }
    if(tid == 0) g_rt[b*80 + o] = red[0];
}
// router stage 2: finalize (tiny)
__global__ void k_route2(const float* __restrict__ base_adj,
                         const float* __restrict__ warp_b, const float* __restrict__ gate_b,
                         float* __restrict__ out_gs, float* __restrict__ out_adj,
                         float* __restrict__ out_mh){
    __shared__ float s_gs[BB][RR];
    int tid = threadIdx.x;   // 32 threads
    if(tid < 32){
        int b = tid/8, i = tid%8;
        float v[8]; float mx = -1e30f;
        for(int j = 0; j < 8; j++){
            v[j] = base_adj[i*8+j] + (g_rt[b*80 + i*8 + j] + warp_b[i*8+j])*0.1f;
            mx = fmaxf(mx, v[j]);
        }
        float sum = 0.f;
        for(int j = 0; j < 8; j++){ v[j] = expf(v[j]-mx); sum += v[j]; }
        float inv = 1.0f/sum;
        float boost = 0.f;
        for(int j = 0; j < 8; j++){
            float a = v[j]*inv;
            out_adj[(b*8+i)*8 + j] = a;
            boost += a*g_rt[b*80 + 64 + j];
        }
        float gl = g_rt[b*80 + 72 + i] + gate_b[i];
        float gs = 1.0f/(1.0f+expf(-(gl+boost)*0.5f));
        out_gs[b*8+i] = gs;
        s_gs[b][i] = gs;
    }
    __syncthreads();
    if(tid == 0){
        float m[RR];
        for(int r = 0; r < 8; r++) m[r] = 0.25f*(s_gs[0][r]+s_gs[1][r]+s_gs[2][r]+s_gs[3][r]);
        for(int h = 0; h < 3; h++){
            int best = 0; float bv = -1e30f;
            for(int r = 0; r < 8; r++) if(m[r] > bv){ bv = m[r]; best = r; }
            g_idx[h] = best; m[best] = -1e30f;
        }
        out_mh[0] = 3.0f;
    }
}

// gate MLP stage 1 (parallel split-K): grid (BB,16) x 256
__global__ void __launch_bounds__(256) k_g1(const float* __restrict__ g1_w, const float* __restrict__ g1_b, int hop){
    int room = g_idx[hop];
    int b = blockIdx.x;
    int tid = threadIdx.x;
    int n = blockIdx.y*16 + (tid & 15);
    int slice = tid >> 4;                 // 16 slices x 64 k
    const float* W = g1_w + (size_t)room*DD*256;
    const float* xv = &g_ctxm[b*DD];
    float s = 0.f;
    int k0 = slice*64;
    for(int k = k0; k < k0+64; k++) s += xv[k]*W[(size_t)k*256 + n];
    __shared__ float red[256];
    red[tid] = s; __syncthreads();
    if(tid < 16){
        float tot = 0.f;
        for(int sl = 0; sl < 16; sl++) tot += red[tid + 16*sl];
        int nn = blockIdx.y*16 + tid;
        g_h1[b*256 + nn] = geluf(tot + g1_b[room*256 + nn]);
    }
}
__global__ void k_g2(const float* __restrict__ g2_w, const float* __restrict__ g2_b, int hop){
    int room = g_idx[hop];
    __shared__ float red[256];
    int tid = threadIdx.x;
    int b = tid/64, lane = tid%64;
    const float* W = g2_w + room*256;
    float s = 0.f;
    for(int k = lane; k < 256; k += 64) s += g_h1[b*256 + k]*W[k];
    red[tid] = s; __syncthreads();
    for(int off = 32; off >= 1; off >>= 1){
        if(lane < off) red[tid] += red[tid+off];
        __syncthreads();
    }
    if(lane == 0){
        float gate = 1.0f/(1.0f+expf(-(red[tid]+g2_b[room])));
        g_gate[b] = gate;
    }
    __syncthreads();
    if(tid == 0) g_gm = 0.25f*(g_gate[0]+g_gate[1]+g_gate[2]+g_gate[3]);
}

// weight pre-pack
__global__ void k_packw(const float* __restrict__ Wb, uint32_t* __restrict__ oh, uint32_t* __restrict__ ol,
                        int N, int hop, long wstr){
    int room = g_idx[hop];
    const float* W = Wb + (size_t)room*wstr;
    int i = blockIdx.x*256 + threadIdx.x;
    int k2 = i / N, n = i % N;
    float a = W[(size_t)(2*k2)*N + n];
    float b = W[(size_t)(2*k2+1)*N + n];
    uint32_t hh, ll; split2(a, b, hh, ll);
    oh[i] = hh; ol[i] = ll;
}

// layernorm -> split bf16 planes
__global__ void __launch_bounds__(256) k_ln2(const float* __restrict__ in,
                     const float* __restrict__ gb, const float* __restrict__ bb,
                     int hop, const float* __restrict__ gate,
                     uint32_t* __restrict__ oh, uint32_t* __restrict__ ol){
    int row = blockIdx.x; int b = row >> 10;
    int room = g_idx[hop];
    float sc = gate ? gate[b] : 1.0f;
    float4 v = ((const float4*)(in + (size_t)row*DD))[threadIdx.x];
    v.x *= sc; v.y *= sc; v.z *= sc; v.w *= sc;
    __shared__ float rs[256], rq[256];
    rs[threadIdx.x] = v.x+v.y+v.z+v.w;
    rq[threadIdx.x] = v.x*v.x+v.y*v.y+v.z*v.z+v.w*v.w;
    __syncthreads();
    for(int off = 128; off >= 1; off >>= 1){
        if(threadIdx.x < off){ rs[threadIdx.x] += rs[threadIdx.x+off]; rq[threadIdx.x] += rq[threadIdx.x+off]; }
        __syncthreads();
    }
    float mean = rs[0]*(1.0f/DD);
    float var  = rq[0]*(1.0f/DD) - mean*mean;
    float inv  = rsqrtf(var + 1e-5f);
    float4 g4 = ((const float4*)(gb + (size_t)room*DD))[threadIdx.x];
    float4 b4 = ((const float4*)(bb + (size_t)room*DD))[threadIdx.x];
    float o0 = (v.x-mean)*inv*g4.x + b4.x;
    float o1 = (v.y-mean)*inv*g4.y + b4.y;
    float o2 = (v.z-mean)*inv*g4.z + b4.z;
    float o3 = (v.w-mean)*inv*g4.w + b4.w;
    uint32_t h0,l0,h1,l1;
    split2(o0,o1,h0,l0); split2(o2,o3,h1,l1);
    size_t w = (size_t)row*512 + threadIdx.x*2;
    *(uint2*)&oh[w] = make_uint2(h0,h1);
    *(uint2*)&ol[w] = make_uint2(l0,l1);
}

// ---------------- shared GEMM core: 3-stage cp.async ring, 1 sync/chunk ----------------
// dyn smem layout (words): sAh[3][128][12], sAl, sBh[3][8][136], sBl
#define SA_OFF(s,r,c) ((s)*1536 + (r)*12 + (c))
#define SB_OFF(s,k,n) ((s)*1088 + (k)*136 + (n))
#define SMEM_WORDS (4608*2 + 3264*2)

__device__ __forceinline__ void gemm_core(
        const uint32_t* __restrict__ Ah_src, const uint32_t* __restrict__ Al_src,
        const uint32_t* __restrict__ Wh_src, const uint32_t* __restrict__ Wl_src,
        int N, int nC, int ar, int ac, int bk, int bc,
        int wm, int wn, int g, int t,
        uint32_t* sAh, uint32_t* sAl, uint32_t* sBh, uint32_t* sBl,
        float acc[2][8][4]){
    // prologue: stages 0,1
    #pragma unroll
    for(int s = 0; s < 2; s++){
        cpa16(sAh + SA_OFF(s,ar,ac), Ah_src + s*8);
        cpa16(sAl + SA_OFF(s,ar,ac), Al_src + s*8);
        cpa16(sBh + SB_OFF(s,bk,bc), Wh_src + (size_t)(s*8)*N);
        cpa16(sBl + SB_OFF(s,bk,bc), Wl_src + (size_t)(s*8)*N);
        CP_COMMIT();
    }
    for(int c = 0; c < nC; c++){
        if(c+1 < nC) asm volatile("cp.async.wait_group 1;");
        else         asm volatile("cp.async.wait_group 0;");
        __syncthreads();
        if(c+2 < nC){
            int s = (c+2)%3;
            int k2o = (c+2)*8;
            cpa16(sAh + SA_OFF(s,ar,ac), Ah_src + k2o);
            cpa16(sAl + SA_OFF(s,ar,ac), Al_src + k2o);
            cpa16(sBh + SB_OFF(s,bk,bc), Wh_src + (size_t)k2o*N);
            cpa16(sBl + SB_OFF(s,bk,bc), Wl_src + (size_t)k2o*N);
            CP_COMMIT();
        }
        int cb = c%3;
        uint32_t ah[2][4], al[2][4];
        #pragma unroll
        for(int mt = 0; mt < 2; mt++){
            int m0 = wm*32 + mt*16;
            ah[mt][0] = sAh[SA_OFF(cb,m0+g  ,t  )]; al[mt][0] = sAl[SA_OFF(cb,m0+g  ,t  )];
            ah[mt][1] = sAh[SA_OFF(cb,m0+g+8,t  )]; al[mt][1] = sAl[SA_OFF(cb,m0+g+8,t  )];
            ah[mt][2] = sAh[SA_OFF(cb,m0+g  ,t+4)]; al[mt][2] = sAl[SA_OFF(cb,m0+g  ,t+4)];
            ah[mt][3] = sAh[SA_OFF(cb,m0+g+8,t+4)]; al[mt][3] = sAl[SA_OFF(cb,m0+g+8,t+4)];
        }
        #pragma unroll
        for(int nt = 0; nt < 8; nt++){
            int n0 = wn*64 + nt*8 + g;
            uint32_t bh0 = sBh[SB_OFF(cb,t  ,n0)], bl0 = sBl[SB_OFF(cb,t  ,n0)];
            uint32_t bh1 = sBh[SB_OFF(cb,t+4,n0)], bl1 = sBl[SB_OFF(cb,t+4,n0)];
            #pragma unroll
            for(int mt = 0; mt < 2; mt++){
                MMA3(acc[mt][nt], ah[mt], al[mt], bh0, bh1, bl0, bl1);
            }
        }
    }
}

// generic GEMM: mode 0: f32 (+res*rscale); mode 1: split planes (opt gelu); mode 2: fused mix
__global__ void __launch_bounds__(256,2) k_gemm3(
        const uint32_t* __restrict__ Ah, const uint32_t* __restrict__ Al,
        const uint32_t* __restrict__ Wh, const uint32_t* __restrict__ Wl,
        const float* __restrict__ bbase, long bstr, int hop,
        const float* __restrict__ res, const float* __restrict__ rscale,
        const float* __restrict__ curin,
        float* __restrict__ C, uint32_t* __restrict__ Ch, uint32_t* __restrict__ Cl,
        int N, int K, int act, int mode){
    extern __shared__ uint32_t smem_u[];
    uint32_t* sAh = smem_u;
    uint32_t* sAl = sAh + 4608;
    uint32_t* sBh = sAl + 4608;
    uint32_t* sBl = sBh + 3264;
    int room = g_idx[hop];
    const float* bias = bbase + (size_t)room*bstr;
    int tid = threadIdx.x;
    int bm = blockIdx.y, bn = blockIdx.x;
    int warp = tid>>5, lane = tid&31;
    int g = lane>>2, t = lane&3;
    int wm = warp>>1, wn = warp&1;
    int halfK = K >> 1;
    int ar = tid>>1, ac = (tid&1)*4;
    int bk = tid>>5, bc = (tid&31)*4;
    const uint32_t* Ah_src = Ah + (size_t)(bm*128 + ar)*halfK + ac;
    const uint32_t* Al_src = Al + (size_t)(bm*128 + ar)*halfK + ac;
    const uint32_t* Wh_src = Wh + (size_t)bk*N + bn*128 + bc;
    const uint32_t* Wl_src = Wl + (size_t)bk*N + bn*128 + bc;

    float acc[2][8][4] = {};
    gemm_core(Ah_src, Al_src, Wh_src, Wl_src, N, K>>4, ar, ac, bk, bc,
              wm, wn, g, t, sAh, sAl, sBh, sBl, acc);

    float gm = (mode == 2) ? g_gm : 0.f;
    #pragma unroll
    for(int mt = 0; mt < 2; mt++){
        int row = bm*128 + wm*32 + mt*16 + g;
        #pragma unroll
        for(int nt = 0; nt < 8; nt++){
            int col = bn*128 + wn*64 + nt*8 + 2*t;
            float2 bi = *(const float2*)&bias[col];
            float v0 = acc[mt][nt][0] + bi.x;
            float v1 = acc[mt][nt][1] + bi.y;
            float v2 = acc[mt][nt][2] + bi.x;
            float v3 = acc[mt][nt][3] + bi.y;
            if(act == 1){
                v0 = geluf(v0); v1 = geluf(v1); v2 = geluf(v2); v3 = geluf(v3);
            }
            size_t i0 = (size_t)row*N + col, i1 = (size_t)(row+8)*N + col;
            if(mode == 0){
                if(res){
                    float sc = rscale ? rscale[row>>10] : 1.0f;
                    float2 r0 = *(const float2*)&res[i0];
                    float2 r1 = *(const float2*)&res[i1];
                    v0 += r0.x*sc; v1 += r0.y*sc; v2 += r1.x*sc; v3 += r1.y*sc;
                }
                *(float2*)&C[i0] = make_float2(v0, v1);
                *(float2*)&C[i1] = make_float2(v2, v3);
            } else if(mode == 1){
                uint32_t hh, ll;
                size_t w0 = (size_t)row*(N>>1) + (col>>1);
                size_t w1 = (size_t)(row+8)*(N>>1) + (col>>1);
                split2(v0, v1, hh, ll); Ch[w0] = hh; Cl[w0] = ll;
                split2(v2, v3, hh, ll); Ch[w1] = hh; Cl[w1] = ll;
            } else {
                float2 r0 = *(const float2*)&res[i0];
                float2 r1 = *(const float2*)&res[i1];
                float2 c0 = *(const float2*)&curin[i0];
                float2 c1 = *(const float2*)&curin[i1];
                float x0 = r0.x + v0, x1 = r0.y + v1, x2 = r1.x + v2, x3 = r1.y + v3;
                *(float2*)&C[i0] = make_float2(c0.x + gm*(x0-c0.x), c0.y + gm*(x1-c0.y));
                *(float2*)&C[i1] = make_float2(c1.x + gm*(x2-c1.x), c1.y + gm*(x3-c1.y));
            }
        }
    }
}

// batched QKV: grid (8,32,3). z=0->q planes, z=1->k planes, z=2->v f32
__global__ void __launch_bounds__(256,2) k_qkv(
        const uint32_t* __restrict__ Ah, const uint32_t* __restrict__ Al,
        const uint32_t* __restrict__ Wp_h, const uint32_t* __restrict__ Wp_l,
        const float* __restrict__ bq, const float* __restrict__ bk_,
        const float* __restrict__ bv, int hop){
    extern __shared__ uint32_t smem_u[];
    uint32_t* sAh = smem_u;
    uint32_t* sAl = sAh + 4608;
    uint32_t* sBh = sAl + 4608;
    uint32_t* sBl = sBh + 3264;
    int room = g_idx[hop];
    int z = blockIdx.z;
    const float* bias = (z==0 ? bq : (z==1 ? bk_ : bv)) + (size_t)room*DD;
    const uint32_t* Wh = Wp_h + (size_t)z*SZP;
    const uint32_t* Wl = Wp_l + (size_t)z*SZP;
    int tid = threadIdx.x;
    int bm = blockIdx.y, bn = blockIdx.x;
    int warp = tid>>5, lane = tid&31;
    int g = lane>>2, t = lane&3;
    int wm = warp>>1, wn = warp&1;
    int ar = tid>>1, ac = (tid&1)*4;
    int bk = tid>>5, bc = (tid&31)*4;
    const uint32_t* Ah_src = Ah + (size_t)(bm*128 + ar)*512 + ac;
    const uint32_t* Al_src = Al + (size_t)(bm*128 + ar)*512 + ac;
    const uint32_t* Wh_src = Wh + (size_t)bk*DD + bn*128 + bc;
    const uint32_t* Wl_src = Wl + (size_t)bk*DD + bn*128 + bc;

    float acc[2][8][4] = {};
    gemm_core(Ah_src, Al_src, Wh_src, Wl_src, DD, 64, ar, ac, bk, bc,
              wm, wn, g, t, sAh, sAl, sBh, sBl, acc);

    uint32_t* Ch = (z==0) ? g_qh : g_kh;
    uint32_t* Cl = (z==0) ? g_ql : g_kl;
    #pragma unroll
    for(int mt = 0; mt < 2; mt++){
        int row = bm*128 + wm*32 + mt*16 + g;
        #pragma unroll
        for(int nt = 0; nt < 8; nt++){
            int col = bn*128 + wn*64 + nt*8 + 2*t;
            float2 bi = *(const float2*)&bias[col];
            float v0 = acc[mt][nt][0] + bi.x;
            float v1 = acc[mt][nt][1] + bi.y;
            float v2 = acc[mt][nt][2] + bi.x;
            float v3 = acc[mt][nt][3] + bi.y;
            size_t i0 = (size_t)row*DD + col, i1 = (size_t)(row+8)*DD + col;
            if(z == 2){
                *(float2*)&g_v[i0] = make_float2(v0, v1);
                *(float2*)&g_v[i1] = make_float2(v2, v3);
            } else {
                uint32_t hh, ll;
                size_t w0 = (size_t)row*512 + (col>>1);
                size_t w1 = (size_t)(row+8)*512 + (col>>1);
                split2(v0, v1, hh, ll); Ch[w0] = hh; Cl[w0] = ll;
                split2(v2, v3, hh, ll); Ch[w1] = hh; Cl[w1] = ll;
            }
        }
    }
}

// ---------------- attention scores ----------------
__global__ void __launch_bounds__(128) k_scores2(){
    int ti = blockIdx.x, tj = blockIdx.y;
    if(tj > ti) return;
    int bh = blockIdx.z; int b = bh>>4, h = bh&15;
    __shared__ uint32_t Qh[64][36], Ql[64][36];
    __shared__ uint32_t Kh[64][36], Kl[64][36];
    int tid = threadIdx.x;
    int warp = tid>>5, lane = tid&31;
    int g = lane>>2, t = lane&3;
    int wm = warp>>1, wn = warp&1;

    #pragma unroll
    for(int i = 0; i < 4; i++){
        int idx = tid + 128*i;
        int r = idx>>3, c = (idx&7)*4;
        size_t qoff = ((size_t)(b*TT + ti*64 + r))*512 + h*32 + c;
        size_t koff = ((size_t)(b*TT + tj*64 + r))*512 + h*32 + c;
        *(uint4*)&Qh[r][c] = *(const uint4*)(g_qh + qoff);
        *(uint4*)&Ql[r][c] = *(const uint4*)(g_ql + qoff);
        *(uint4*)&Kh[r][c] = *(const uint4*)(g_kh + koff);
        *(uint4*)&Kl[r][c] = *(const uint4*)(g_kl + koff);
    }
    __syncthreads();

    float acc[2][4][4] = {};
    #pragma unroll
    for(int kk2 = 0; kk2 < 32; kk2 += 8){
        uint32_t ah[2][4], al[2][4];
        #pragma unroll
        for(int mt = 0; mt < 2; mt++){
            int m0 = wm*32 + mt*16;
            ah[mt][0] = Qh[m0+g  ][kk2+t  ]; al[mt][0] = Ql[m0+g  ][kk2+t  ];
            ah[mt][1] = Qh[m0+g+8][kk2+t  ]; al[mt][1] = Ql[m0+g+8][kk2+t  ];
            ah[mt][2] = Qh[m0+g  ][kk2+t+4]; al[mt][2] = Ql[m0+g  ][kk2+t+4];
            ah[mt][3] = Qh[m0+g+8][kk2+t+4]; al[mt][3] = Ql[m0+g+8][kk2+t+4];
        }
        #pragma unroll
        for(int nt = 0; nt < 4; nt++){
            int n0 = wn*32 + nt*8 + g;
            uint32_t bh0 = Kh[n0][kk2+t  ], bl0 = Kl[n0][kk2+t  ];
            uint32_t bh1 = Kh[n0][kk2+t+4], bl1 = Kl[n0][kk2+t+4];
            #pragma unroll
            for(int mt = 0; mt < 2; mt++){
                MMA3(acc[mt][nt], ah[mt], al[mt], bh0, bh1, bl0, bl1);
            }
        }
    }
    #pragma unroll
    for(int mt = 0; mt < 2; mt++){
        int row = ti*64 + wm*32 + mt*16 + g;
        #pragma unroll
        for(int nt = 0; nt < 4; nt++){
            int col = tj*64 + wn*32 + nt*8 + 2*t;
            float* sp = g_attn + ((size_t)bh*TT + row)*TT + col;
            *(float2*)sp = make_float2(acc[mt][nt][0]*0.125f, acc[mt][nt][1]*0.125f);
            *(float2*)(sp + (size_t)8*TT) = make_float2(acc[mt][nt][2]*0.125f, acc[mt][nt][3]*0.125f);
        }
    }
}

__global__ void __launch_bounds__(128) k_softmax2(){
    int row = blockIdx.x;
    int i = row & (TT-1);
    const float* p = g_attn + (size_t)row*TT;
    __nv_bfloat16* ph = g_ph + (size_t)row*TT;
    __nv_bfloat16* pl = g_pl + (size_t)row*TT;
    int len = i+1, tid = threadIdx.x;
    int tend = ((i>>6)+1)<<6;
    __shared__ float red[128];
    float mx = -1e30f;
    for(int j = tid; j < len; j += 128) mx = fmaxf(mx, p[j]);
    red[tid] = mx; __syncthreads();
    for(int off = 64; off >= 1; off >>= 1){
        if(tid < off) red[tid] = fmaxf(red[tid], red[tid+off]);
        __syncthreads();
    }
    mx = red[0]; __syncthreads();
    float s = 0.f;
    for(int j = tid; j < len; j += 128) s += expf(p[j]-mx);
    red[tid] = s; __syncthreads();
    for(int off = 64; off >= 1; off >>= 1){
        if(tid < off) red[tid] += red[tid+off];
        __syncthreads();
    }
    float inv = 1.0f/red[0];
    for(int j = tid; j < len; j += 128){
        float e = expf(p[j]-mx)*inv;
        __nv_bfloat16 hb = __float2bfloat16_rn(e);
        ph[j] = hb;
        pl[j] = __float2bfloat16_rn(e - __bfloat162float(hb));
    }
    __nv_bfloat16 z = __float2bfloat16_rn(0.f);
    for(int j = len + tid; j < tend; j += 128){ ph[j] = z; pl[j] = z; }
}

__global__ void __launch_bounds__(128) k_av2(const float* __restrict__ v){
    int ti = blockIdx.x; int bh = blockIdx.y;
    int b = bh>>4, h = bh&15;
    __shared__ uint32_t Ph[64][36], Pl[64][36];
    __shared__ uint32_t Vh[32][72], Vl[32][72];
    int tid = threadIdx.x;
    int warp = tid>>5, lane = tid&31;
    int g = lane>>2, t = lane&3;
    int wm = warp>>1, wn = warp&1;
    int vk2 = tid>>4, vn4 = tid&15;

    const uint32_t* phw = (const uint32_t*)g_ph;
    const uint32_t* plw = (const uint32_t*)g_pl;

    float acc[2][4][4] = {};
    for(int kt = 0; kt <= ti; kt++){
        #pragma unroll
        for(int i = 0; i < 4; i++){
            int idx = tid + 128*i;
            int r = idx>>3, c = (idx&7)*4;
            size_t poff = ((size_t)bh*TT + ti*64 + r)*512 + kt*32 + c;
            *(uint4*)&Ph[r][c] = *(const uint4*)(phw + poff);
            *(uint4*)&Pl[r][c] = *(const uint4*)(plw + poff);
        }
        #pragma unroll
        for(int i = 0; i < 4; i++){
            int k2 = vk2 + 8*i;
            const float* v0 = v + (size_t)(b*TT + kt*64 + 2*k2  )*DD + h*64 + vn4*4;
            const float* v1 = v + (size_t)(b*TT + kt*64 + 2*k2+1)*DD + h*64 + vn4*4;
            float4 a4 = *(const float4*)v0;
            float4 b4 = *(const float4*)v1;
            const float* r0 = (const float*)&a4;
            const float* r1 = (const float*)&b4;
            uint32_t hh[4], ll[4];
            #pragma unroll
            for(int j = 0; j < 4; j++) split2(r0[j], r1[j], hh[j], ll[j]);
            *(uint4*)&Vh[k2][vn4*4] = make_uint4(hh[0],hh[1],hh[2],hh[3]);
            *(uint4*)&Vl[k2][vn4*4] = make_uint4(ll[0],ll[1],ll[2],ll[3]);
        }
        __syncthreads();
        #pragma unroll
        for(int kk2 = 0; kk2 < 32; kk2 += 8){
            uint32_t ah[2][4], al[2][4];
            #pragma unroll
            for(int mt = 0; mt < 2; mt++){
                int m0 = wm*32 + mt*16;
                ah[mt][0] = Ph[m0+g  ][kk2+t  ]; al[mt][0] = Pl[m0+g  ][kk2+t  ];
                ah[mt][1] = Ph[m0+g+8][kk2+t  ]; al[mt][1] = Pl[m0+g+8][kk2+t  ];
                ah[mt][2] = Ph[m0+g  ][kk2+t+4]; al[mt][2] = Pl[m0+g  ][kk2+t+4];
                ah[mt][3] = Ph[m0+g+8][kk2+t+4]; al[mt][3] = Pl[m0+g+8][kk2+t+4];
            }
            #pragma unroll
            for(int nt = 0; nt < 4; nt++){
                int n0 = wn*32 + nt*8 + g;
                uint32_t bh0 = Vh[kk2+t  ][n0], bl0 = Vl[kk2+t  ][n0];
                uint32_t bh1 = Vh[kk2+t+4][n0], bl1 = Vl[kk2+t+4][n0];
                #pragma unroll
                for(int mt = 0; mt < 2; mt++){
                    MMA3(acc[mt][nt], ah[mt], al[mt], bh0, bh1, bl0, bl1);
                }
            }
        }
        __syncthreads();
    }
    #pragma unroll
    for(int mt = 0; mt < 2; mt++){
        int row = ti*64 + wm*32 + mt*16 + g;
        #pragma unroll
        for(int nt = 0; nt < 4; nt++){
            int col = wn*32 + nt*8 + 2*t;
            size_t w0 = ((size_t)(b*TT + row))*512 + (h*64 + col)/2;
            size_t w1 = ((size_t)(b*TT + row + 8))*512 + (h*64 + col)/2;
            uint32_t hh, ll;
            split2(acc[mt][nt][0], acc[mt][nt][1], hh, ll);
            g_oh[w0] = hh; g_ol[w0] = ll;
            split2(acc[mt][nt][2], acc[mt][nt][3], hh, ll);
            g_oh[w1] = hh; g_ol[w1] = ll;
        }
    }
}

extern "C" void kernel_launch(void* const* d_in, const int* in_sizes, int n_in,
                              void* d_out, int out_size){
    const float* x         = (const float*)d_in[0];
    const float* summaries = (const float*)d_in[1];
    const float* ctx_w     = (const float*)d_in[2];
    const float* ctx_b     = (const float*)d_in[3];
    const float* base_adj  = (const float*)d_in[4];
    const float* warp_w    = (const float*)d_in[5];
    const float* warp_b    = (const float*)d_in[6];
    const float* gate_w    = (const float*)d_in[7];
    const float* gate_b    = (const float*)d_in[8];
    const float* g1_w      = (const float*)d_in[9];
    const float* g1_b      = (const float*)d_in[10];
    const float* g2_w      = (const float*)d_in[11];
    const float* g2_b      = (const float*)d_in[12];
    const float* ln1_g     = (const float*)d_in[13];
    const float* ln1_b     = (const float*)d_in[14];
    const float* wq        = (const float*)d_in[15];
    const float* bq        = (const float*)d_in[16];
    const float* wk        = (const float*)d_in[17];
    const float* bk        = (const float*)d_in[18];
    const float* wv        = (const float*)d_in[19];
    const float* bv        = (const float*)d_in[20];
    const float* wo        = (const float*)d_in[21];
    const float* bo        = (const float*)d_in[22];
    const float* ln2_g     = (const float*)d_in[23];
    const float* ln2_b     = (const float*)d_in[24];
    const float* ff1_w     = (const float*)d_in[25];
    const float* ff1_b     = (const float*)d_in[26];
    const float* ff2_w     = (const float*)d_in[27];
    const float* ff2_b     = (const float*)d_in[28];
    float* out = (float*)d_out;

    float *p_cur, *p_xo, *p_v, *p_gate;
    uint32_t *p_oh,*p_ol,*p_nh,*p_nl,*p_mh,*p_ml,*p_wph,*p_wpl;
    cudaGetSymbolAddress((void**)&p_cur,  g_cur);
    cudaGetSymbolAddress((void**)&p_xo,   g_xo);
    cudaGetSymbolAddress((void**)&p_v,    g_v);
    cudaGetSymbolAddress((void**)&p_gate, g_gate);
    cudaGetSymbolAddress((void**)&p_oh, g_oh);  cudaGetSymbolAddress((void**)&p_ol, g_ol);
    cudaGetSymbolAddress((void**)&p_nh, g_normh); cudaGetSymbolAddress((void**)&p_nl, g_norml);
    cudaGetSymbolAddress((void**)&p_mh, g_midh); cudaGetSymbolAddress((void**)&p_ml, g_midl);
    cudaGetSymbolAddress((void**)&p_wph, g_wph); cudaGetSymbolAddress((void**)&p_wpl, g_wpl);

    const int SMEM_B = SMEM_WORDS*4;
    cudaFuncSetAttribute(k_gemm3, cudaFuncAttributeMaxDynamicSharedMemorySize, SMEM_B);
    cudaFuncSetAttribute(k_qkv,   cudaFuncAttributeMaxDynamicSharedMemorySize, SMEM_B);

    // ---- router ----
    k_meanT_part<<<dim3(BB,32),256>>>(x);
    k_meanT_reduce<<<BB,256>>>();
    k_ctx<<<dim3(BB,32),128>>>(ctx_w, ctx_b);
    k_route1<<<dim3(BB,80),128>>>(warp_w, summaries, gate_w);
    k_route2<<<1,32>>>(base_adj, warp_b, gate_b,
                       out + BTD, out + BTD + 32, out + BTD + 32 + 256);

    // ---- 3 hops ----
    for(int hop = 0; hop < 3; hop++){
        const float* cin = (hop == 0) ? x : p_cur;
        float* cout = (hop == 2) ? out : p_cur;

        k_packw<<<SZP/256,256>>>(wq,  p_wph+0*SZP, p_wpl+0*SZP, DD,  hop, (long)DD*DD);
        k_packw<<<SZP/256,256>>>(wk,  p_wph+1*SZP, p_wpl+1*SZP, DD,  hop, (long)DD*DD);
        k_packw<<<SZP/256,256>>>(wv,  p_wph+2*SZP, p_wpl+2*SZP, DD,  hop, (long)DD*DD);
        k_packw<<<SZP/256,256>>>(wo,  p_wph+3*SZP, p_wpl+3*SZP, DD,  hop, (long)DD*DD);
        k_packw<<<SZF/256,256>>>(ff1_w, p_wph+4*SZP,     p_wpl+4*SZP,     DFF, hop, (long)DD*DFF);
        k_packw<<<SZF/256,256>>>(ff2_w, p_wph+4*SZP+SZF, p_wpl+4*SZP+SZF, DD,  hop, (long)DFF*DD);

        if(hop > 0){
            k_meanT_part<<<dim3(BB,32),256>>>(cin);
            k_meanT_reduce<<<BB,256>>>();
        }
        k_g1<<<dim3(BB,16),256>>>(g1_w, g1_b, hop);
        k_g2<<<1,256>>>(g2_w, g2_b, hop);
        k_ln2<<<BT,256>>>(cin, ln1_g, ln1_b, hop, p_gate, p_nh, p_nl);
        // batched q,k,v
        k_qkv<<<dim3(8,32,3),256,SMEM_B>>>(p_nh, p_nl, p_wph, p_wpl, bq, bk, bv, hop);
        // attention
        k_scores2<<<dim3(16,16,BB*HH),128>>>();
        k_softmax2<<<BB*HH*TT,128>>>();
        k_av2<<<dim3(16,BB*HH),128>>>(p_v);
        // xo = cur*gate + o@wo + bo
        k_gemm3<<<dim3(8,32),256,SMEM_B>>>(p_oh,p_ol, p_wph+3*SZP,p_wpl+3*SZP, bo, DD, hop,
                                    cin, p_gate, nullptr, p_xo, nullptr,nullptr, DD, DD, 0, 0);
        // ffn
        k_ln2<<<BT,256>>>(p_xo, ln2_g, ln2_b, hop, nullptr, p_nh, p_nl);
        k_gemm3<<<dim3(32,32),256,SMEM_B>>>(p_nh,p_nl, p_wph+4*SZP,p_wpl+4*SZP, ff1_b, DFF, hop,
                                    nullptr,nullptr,nullptr, nullptr, p_mh,p_ml, DFF, DD, 1, 1);
        k_gemm3<<<dim3(8,32),256,SMEM_B>>>(p_mh,p_ml, p_wph+4*SZP+SZF,p_wpl+4*SZP+SZF, ff2_b, DD, hop,
                                    p_xo, nullptr, cin, cout, nullptr,nullptr, DD, DFF, 0, 2);
    }
}

// round 9
// speedup vs baseline: 3.1007x; 1.2117x over previous
#include <cuda_runtime.h>
#include <cuda_bf16.h>
#include <math.h>
#include <stdint.h>

#define BB 4
#define TT 1024
#define DD 1024
#define HH 16
#define DFF 4096
#define RR 8
#define BT (BB*TT)
#define BTD (BB*TT*DD)
#define SZP (512*1024)
#define SZF 2097152

// ---------------- device scratch ----------------
__device__ float g_cur[BTD];
__device__ float g_xo[BTD];
__device__ float g_v[BTD];
__device__ uint32_t g_qh[BT*512], g_ql[BT*512];
__device__ uint32_t g_kh[BT*512], g_kl[BT*512];
__device__ uint32_t g_oh[BT*512], g_ol[BT*512];
__device__ uint32_t g_normh[BT*512], g_norml[BT*512];
__device__ uint32_t g_midh[BT*2048], g_midl[BT*2048];
__device__ uint32_t g_wph[4*SZP + 2*SZF], g_wpl[4*SZP + 2*SZF];
__device__ float g_part[BB*32*DD];
__device__ float g_ctxm[BB*DD];
__device__ float g_ctx[BB*DD];
__device__ float g_rt[BB*80];
__device__ float g_h1[BB*256];
__device__ float g_gate[BB];
__device__ float g_gm;
__device__ int   g_idx[3];

__device__ __forceinline__ float geluf(float x){
    return 0.5f*x*(1.0f+erff(x*0.7071067811865476f));
}
__device__ __forceinline__ void split2(float x, float y, uint32_t &hi, uint32_t &lo){
    __nv_bfloat16 xh = __float2bfloat16_rn(x);
    __nv_bfloat16 yh = __float2bfloat16_rn(y);
    __nv_bfloat162 h; h.x = xh; h.y = yh;
    __nv_bfloat162 l; l.x = __float2bfloat16_rn(x - __bfloat162float(xh));
    l.y = __float2bfloat16_rn(y - __bfloat162float(yh));
    hi = *(uint32_t*)&h; lo = *(uint32_t*)&l;
}
__device__ __forceinline__ void mma_bf16(float* c, uint32_t a0, uint32_t a1, uint32_t a2, uint32_t a3,
                                         uint32_t b0, uint32_t b1){
    asm volatile("mma.sync.aligned.m16n8k16.row.col.f32.bf16.bf16.f32 "
        "{%0,%1,%2,%3},{%4,%5,%6,%7},{%8,%9},{%0,%1,%2,%3};"
        : "+f"(c[0]), "+f"(c[1]), "+f"(c[2]), "+f"(c[3])
        : "r"(a0), "r"(a1), "r"(a2), "r"(a3), "r"(b0), "r"(b1));
}
#define MMA3(accp, AH, AL, BH0, BH1, BL0, BL1) \
    mma_bf16(accp, AH[0],AH[1],AH[2],AH[3], BH0, BH1); \
    mma_bf16(accp, AH[0],AH[1],AH[2],AH[3], BL0, BL1); \
    mma_bf16(accp, AL[0],AL[1],AL[2],AL[3], BH0, BH1);

__device__ __forceinline__ void cpa16(void* dst, const void* src){
    uint32_t d = (uint32_t)__cvta_generic_to_shared(dst);
    asm volatile("cp.async.cg.shared.global [%0], [%1], 16;" :: "r"(d), "l"(src));
}
#define CP_COMMIT() asm volatile("cp.async.commit_group;")

// ---------------- small kernels ----------------
__global__ void k_meanT_part(const float* __restrict__ in){
    int b = blockIdx.x, c = blockIdx.y;
    int t0 = c*32;
    for(int d = threadIdx.x; d < DD; d += 256){
        float s = 0.f;
        for(int t = t0; t < t0+32; t++) s += in[((size_t)(b*TT+t))*DD + d];
        g_part[(size_t)(b*32+c)*DD + d] = s;
    }
}
__global__ void k_meanT_reduce(){
    int b = blockIdx.x;
    for(int d = threadIdx.x; d < DD; d += 256){
        float s = 0.f;
        for(int c = 0; c < 32; c++) s += g_part[(size_t)(b*32+c)*DD + d];
        g_ctxm[b*DD + d] = s*(1.0f/TT);
    }
}
__global__ void k_ctx(const float* __restrict__ W, const float* __restrict__ bias){
    int b = blockIdx.x; int n0 = blockIdx.y*32;
    int lane = threadIdx.x & 31, q = threadIdx.x >> 5;
    const float* xv = &g_ctxm[b*DD];
    float s = 0.f;
    int k0 = q*256;
    for(int k = k0; k < k0+256; k++) s += xv[k]*W[(size_t)k*DD + n0 + lane];
    __shared__ float red[4][32];
    red[q][lane] = s; __syncthreads();
    if(q == 0)
        g_ctx[b*DD + n0 + lane] = red[0][lane]+red[1][lane]+red[2][lane]+red[3][lane] + bias[n0+lane];
}
__global__ void __launch_bounds__(128) k_route1(const float* __restrict__ warp_w,
        const float* __restrict__ summaries, const float* __restrict__ gate_w){
    int b = blockIdx.x, o = blockIdx.y;
    int tid = threadIdx.x;
    const float* xv = &g_ctx[b*DD];
    float s = 0.f;
    if(o < 64){
        for(int k = tid; k < DD; k += 128) s += xv[k]*warp_w[(size_t)k*64 + o];
    } else if(o < 72){
        const float* sr = summaries + (size_t)(o-64)*DD;
        for(int k = tid; k < DD; k += 128) s += xv[k]*sr[k];
    } else {
        for(int k = tid; k < DD; k += 128) s += xv[k]*gate_w[k*RR + (o-72)];
    }
    __shared__ float red[128];
    red[tid] = s; __syncthreads();
    for(int off = 64; off >= 1; off >>= 1){
        if(tid < off) red[tid] += red[tid+off];
        __syncthreads();
    }
    if(tid == 0) g_rt[b*80 + o] = red[0];
}
__global__ void k_route2(const float* __restrict__ base_adj,
                         const float* __restrict__ warp_b, const float* __restrict__ gate_b,
                         float* __restrict__ out_gs, float* __restrict__ out_adj,
                         float* __restrict__ out_mh){
    __shared__ float s_gs[BB][RR];
    int tid = threadIdx.x;
    if(tid < 32){
        int b = tid/8, i = tid%8;
        float v[8]; float mx = -1e30f;
        for(int j = 0; j < 8; j++){
            v[j] = base_adj[i*8+j] + (g_rt[b*80 + i*8 + j] + warp_b[i*8+j])*0.1f;
            mx = fmaxf(mx, v[j]);
        }
        float sum = 0.f;
        for(int j = 0; j < 8; j++){ v[j] = expf(v[j]-mx); sum += v[j]; }
        float inv = 1.0f/sum;
        float boost = 0.f;
        for(int j = 0; j < 8; j++){
            float a = v[j]*inv;
            out_adj[(b*8+i)*8 + j] = a;
            boost += a*g_rt[b*80 + 64 + j];
        }
        float gl = g_rt[b*80 + 72 + i] + gate_b[i];
        float gs = 1.0f/(1.0f+expf(-(gl+boost)*0.5f));
        out_gs[b*8+i] = gs;
        s_gs[b][i] = gs;
    }
    __syncthreads();
    if(tid == 0){
        float m[RR];
        for(int r = 0; r < 8; r++) m[r] = 0.25f*(s_gs[0][r]+s_gs[1][r]+s_gs[2][r]+s_gs[3][r]);
        for(int h = 0; h < 3; h++){
            int best = 0; float bv = -1e30f;
            for(int r = 0; r < 8; r++) if(m[r] > bv){ bv = m[r]; best = r; }
            g_idx[h] = best; m[best] = -1e30f;
        }
        out_mh[0] = 3.0f;
    }
}
__global__ void __launch_bounds__(256) k_g1(const float* __restrict__ g1_w, const float* __restrict__ g1_b, int hop){
    int room = g_idx[hop];
    int b = blockIdx.x;
    int tid = threadIdx.x;
    int n = blockIdx.y*16 + (tid & 15);
    int slice = tid >> 4;
    const float* W = g1_w + (size_t)room*DD*256;
    const float* xv = &g_ctxm[b*DD];
    float s = 0.f;
    int k0 = slice*64;
    for(int k = k0; k < k0+64; k++) s += xv[k]*W[(size_t)k*256 + n];
    __shared__ float red[256];
    red[tid] = s; __syncthreads();
    if(tid < 16){
        float tot = 0.f;
        for(int sl = 0; sl < 16; sl++) tot += red[tid + 16*sl];
        int nn = blockIdx.y*16 + tid;
        g_h1[b*256 + nn] = geluf(tot + g1_b[room*256 + nn]);
    }
}
__global__ void k_g2(const float* __restrict__ g2_w, const float* __restrict__ g2_b, int hop){
    int room = g_idx[hop];
    __shared__ float red[256];
    int tid = threadIdx.x;
    int b = tid/64, lane = tid%64;
    const float* W = g2_w + room*256;
    float s = 0.f;
    for(int k = lane; k < 256; k += 64) s += g_h1[b*256 + k]*W[k];
    red[tid] = s; __syncthreads();
    for(int off = 32; off >= 1; off >>= 1){
        if(lane < off) red[tid] += red[tid+off];
        __syncthreads();
    }
    if(lane == 0){
        float gate = 1.0f/(1.0f+expf(-(red[tid]+g2_b[room])));
        g_gate[b] = gate;
    }
    __syncthreads();
    if(tid == 0) g_gm = 0.25f*(g_gate[0]+g_gate[1]+g_gate[2]+g_gate[3]);
}

// weight pre-pack: vertical k-pairs, layout [K/2][N]
__global__ void k_packw(const float* __restrict__ Wb, uint32_t* __restrict__ oh, uint32_t* __restrict__ ol,
                        int N, int hop, long wstr){
    int room = g_idx[hop];
    const float* W = Wb + (size_t)room*wstr;
    int i = blockIdx.x*256 + threadIdx.x;
    int k2 = i / N, n = i % N;
    float a = W[(size_t)(2*k2)*N + n];
    float b = W[(size_t)(2*k2+1)*N + n];
    uint32_t hh, ll; split2(a, b, hh, ll);
    oh[i] = hh; ol[i] = ll;
}

// layernorm -> split bf16 planes
__global__ void __launch_bounds__(256) k_ln2(const float* __restrict__ in,
                     const float* __restrict__ gb, const float* __restrict__ bb,
                     int hop, const float* __restrict__ gate,
                     uint32_t* __restrict__ oh, uint32_t* __restrict__ ol){
    int row = blockIdx.x; int b = row >> 10;
    int room = g_idx[hop];
    float sc = gate ? gate[b] : 1.0f;
    float4 v = ((const float4*)(in + (size_t)row*DD))[threadIdx.x];
    v.x *= sc; v.y *= sc; v.z *= sc; v.w *= sc;
    __shared__ float rs[256], rq[256];
    rs[threadIdx.x] = v.x+v.y+v.z+v.w;
    rq[threadIdx.x] = v.x*v.x+v.y*v.y+v.z*v.z+v.w*v.w;
    __syncthreads();
    for(int off = 128; off >= 1; off >>= 1){
        if(threadIdx.x < off){ rs[threadIdx.x] += rs[threadIdx.x+off]; rq[threadIdx.x] += rq[threadIdx.x+off]; }
        __syncthreads();
    }
    float mean = rs[0]*(1.0f/DD);
    float var  = rq[0]*(1.0f/DD) - mean*mean;
    float inv  = rsqrtf(var + 1e-5f);
    float4 g4 = ((const float4*)(gb + (size_t)room*DD))[threadIdx.x];
    float4 b4 = ((const float4*)(bb + (size_t)room*DD))[threadIdx.x];
    float o0 = (v.x-mean)*inv*g4.x + b4.x;
    float o1 = (v.y-mean)*inv*g4.y + b4.y;
    float o2 = (v.z-mean)*inv*g4.z + b4.z;
    float o3 = (v.w-mean)*inv*g4.w + b4.w;
    uint32_t h0,l0,h1,l1;
    split2(o0,o1,h0,l0); split2(o2,o3,h1,l1);
    size_t w = (size_t)row*512 + threadIdx.x*2;
    *(uint2*)&oh[w] = make_uint2(h0,h1);
    *(uint2*)&ol[w] = make_uint2(l0,l1);
}

// ---------------- GEMM core: BK=32, 3-stage cp.async ring ----------------
// words: sAh[3][128][20] (stride 20 = 80B, 16B-aligned rows), sBh[3][16][136]
#define SA_OFF(s,r,c) ((s)*2560 + (r)*20 + (c))
#define SB_OFF(s,k,c) ((s)*2176 + (k)*136 + (c))
#define DSMEM_BYTES ((7680*2 + 6528*2)*4)

__device__ __forceinline__ void gemm_core(
        const uint32_t* __restrict__ Ah, const uint32_t* __restrict__ Al,
        const uint32_t* __restrict__ Wh, const uint32_t* __restrict__ Wl,
        int N, int K, int bm, int bn,
        uint32_t* sAh, uint32_t* sAl, uint32_t* sBh, uint32_t* sBl,
        float acc[2][8][4], int tid, int wm, int wn, int g, int t){
    int halfK = K >> 1;
    int nC = K >> 5;
    int arA = tid>>2, acA = (tid&3)*4;      // rows arA, arA+64
    int brA = tid>>5, bcA = (tid&31)*4;     // k2 rows brA, brA+8
    const uint32_t* AhS = Ah + (size_t)(bm*128 + arA)*halfK + acA;
    const uint32_t* AlS = Al + (size_t)(bm*128 + arA)*halfK + acA;
    const uint32_t* WhS = Wh + (size_t)brA*N + bn*128 + bcA;
    const uint32_t* WlS = Wl + (size_t)brA*N + bn*128 + bcA;
    const size_t a64 = (size_t)64*halfK;
    const size_t b8  = (size_t)8*N;

    #pragma unroll
    for(int s = 0; s < 2; s++){
        if(s < nC){
            int k0w = s*16;
            cpa16(sAh + SA_OFF(s,arA,acA), AhS + k0w);
            cpa16(sAh + SA_OFF(s,arA+64,acA), AhS + a64 + k0w);
            cpa16(sAl + SA_OFF(s,arA,acA), AlS + k0w);
            cpa16(sAl + SA_OFF(s,arA+64,acA), AlS + a64 + k0w);
            cpa16(sBh + SB_OFF(s,brA,bcA), WhS + (size_t)k0w*N);
            cpa16(sBh + SB_OFF(s,brA+8,bcA), WhS + (size_t)k0w*N + b8);
            cpa16(sBl + SB_OFF(s,brA,bcA), WlS + (size_t)k0w*N);
            cpa16(sBl + SB_OFF(s,brA+8,bcA), WlS + (size_t)k0w*N + b8);
            CP_COMMIT();
        }
    }
    for(int c = 0; c < nC; c++){
        if(c+1 < nC) asm volatile("cp.async.wait_group 1;");
        else         asm volatile("cp.async.wait_group 0;");
        __syncthreads();
        if(c+2 < nC){
            int s = (c+2)%3;
            int k0w = (c+2)*16;
            cpa16(sAh + SA_OFF(s,arA,acA), AhS + k0w);
            cpa16(sAh + SA_OFF(s,arA+64,acA), AhS + a64 + k0w);
            cpa16(sAl + SA_OFF(s,arA,acA), AlS + k0w);
            cpa16(sAl + SA_OFF(s,arA+64,acA), AlS + a64 + k0w);
            cpa16(sBh + SB_OFF(s,brA,bcA), WhS + (size_t)k0w*N);
            cpa16(sBh + SB_OFF(s,brA+8,bcA), WhS + (size_t)k0w*N + b8);
            cpa16(sBl + SB_OFF(s,brA,bcA), WlS + (size_t)k0w*N);
            cpa16(sBl + SB_OFF(s,brA+8,bcA), WlS + (size_t)k0w*N + b8);
            CP_COMMIT();
        }
        int cb = c%3;
        #pragma unroll
        for(int kk2 = 0; kk2 < 16; kk2 += 8){
            uint32_t ah[2][4], al[2][4];
            #pragma unroll
            for(int mt = 0; mt < 2; mt++){
                int m0 = wm*32 + mt*16;
                ah[mt][0] = sAh[SA_OFF(cb,m0+g  ,kk2+t  )]; al[mt][0] = sAl[SA_OFF(cb,m0+g  ,kk2+t  )];
                ah[mt][1] = sAh[SA_OFF(cb,m0+g+8,kk2+t  )]; al[mt][1] = sAl[SA_OFF(cb,m0+g+8,kk2+t  )];
                ah[mt][2] = sAh[SA_OFF(cb,m0+g  ,kk2+t+4)]; al[mt][2] = sAl[SA_OFF(cb,m0+g  ,kk2+t+4)];
                ah[mt][3] = sAh[SA_OFF(cb,m0+g+8,kk2+t+4)]; al[mt][3] = sAl[SA_OFF(cb,m0+g+8,kk2+t+4)];
            }
            #pragma unroll
            for(int nt = 0; nt < 8; nt++){
                int n0 = wn*64 + nt*8 + g;
                uint32_t bh0 = sBh[SB_OFF(cb,kk2+t  ,n0)], bl0 = sBl[SB_OFF(cb,kk2+t  ,n0)];
                uint32_t bh1 = sBh[SB_OFF(cb,kk2+t+4,n0)], bl1 = sBl[SB_OFF(cb,kk2+t+4,n0)];
                #pragma unroll
                for(int mt = 0; mt < 2; mt++){
                    MMA3(acc[mt][nt], ah[mt], al[mt], bh0, bh1, bl0, bl1);
                }
            }
        }
        __syncthreads();
    }
}

// generic GEMM: mode 0: f32 (+res*rscale); mode 1: split planes (opt gelu); mode 2: fused mix
__global__ void __launch_bounds__(256,2) k_gemm3(
        const uint32_t* __restrict__ Ah, const uint32_t* __restrict__ Al,
        const uint32_t* __restrict__ Wh, const uint32_t* __restrict__ Wl,
        const float* __restrict__ bbase, long bstr, int hop,
        const float* __restrict__ res, const float* __restrict__ rscale,
        const float* __restrict__ curin,
        float* __restrict__ C, uint32_t* __restrict__ Ch, uint32_t* __restrict__ Cl,
        int N, int K, int act, int mode){
    extern __shared__ uint32_t smem_u[];
    uint32_t* sAh = smem_u;
    uint32_t* sAl = sAh + 7680;
    uint32_t* sBh = sAl + 7680;
    uint32_t* sBl = sBh + 6528;
    int room = g_idx[hop];
    const float* bias = bbase + (size_t)room*bstr;
    int tid = threadIdx.x;
    int bm = blockIdx.y, bn = blockIdx.x;
    int warp = tid>>5, lane = tid&31;
    int g = lane>>2, t = lane&3;
    int wm = warp>>1, wn = warp&1;

    float acc[2][8][4] = {};
    gemm_core(Ah, Al, Wh, Wl, N, K, bm, bn, sAh, sAl, sBh, sBl, acc, tid, wm, wn, g, t);

    float gm = (mode == 2) ? g_gm : 0.f;
    #pragma unroll
    for(int mt = 0; mt < 2; mt++){
        int row = bm*128 + wm*32 + mt*16 + g;
        #pragma unroll
        for(int nt = 0; nt < 8; nt++){
            int col = bn*128 + wn*64 + nt*8 + 2*t;
            float2 bi = *(const float2*)&bias[col];
            float v0 = acc[mt][nt][0] + bi.x;
            float v1 = acc[mt][nt][1] + bi.y;
            float v2 = acc[mt][nt][2] + bi.x;
            float v3 = acc[mt][nt][3] + bi.y;
            if(act == 1){
                v0 = geluf(v0); v1 = geluf(v1); v2 = geluf(v2); v3 = geluf(v3);
            }
            size_t i0 = (size_t)row*N + col, i1 = (size_t)(row+8)*N + col;
            if(mode == 0){
                if(res){
                    float sc = rscale ? rscale[row>>10] : 1.0f;
                    float2 r0 = *(const float2*)&res[i0];
                    float2 r1 = *(const float2*)&res[i1];
                    v0 += r0.x*sc; v1 += r0.y*sc; v2 += r1.x*sc; v3 += r1.y*sc;
                }
                *(float2*)&C[i0] = make_float2(v0, v1);
                *(float2*)&C[i1] = make_float2(v2, v3);
            } else if(mode == 1){
                uint32_t hh, ll;
                size_t w0 = (size_t)row*(N>>1) + (col>>1);
                size_t w1 = (size_t)(row+8)*(N>>1) + (col>>1);
                split2(v0, v1, hh, ll); Ch[w0] = hh; Cl[w0] = ll;
                split2(v2, v3, hh, ll); Ch[w1] = hh; Cl[w1] = ll;
            } else {
                float2 r0 = *(const float2*)&res[i0];
                float2 r1 = *(const float2*)&res[i1];
                float2 c0 = *(const float2*)&curin[i0];
                float2 c1 = *(const float2*)&curin[i1];
                float x0 = r0.x + v0, x1 = r0.y + v1, x2 = r1.x + v2, x3 = r1.y + v3;
                *(float2*)&C[i0] = make_float2(c0.x + gm*(x0-c0.x), c0.y + gm*(x1-c0.y));
                *(float2*)&C[i1] = make_float2(c1.x + gm*(x2-c1.x), c1.y + gm*(x3-c1.y));
            }
        }
    }
}

// batched QKV: grid (8,32,3). z=0 -> q planes, z=1 -> k planes, z=2 -> v f32
__global__ void __launch_bounds__(256,2) k_qkv(
        const uint32_t* __restrict__ Ah, const uint32_t* __restrict__ Al,
        const uint32_t* __restrict__ Wp_h, const uint32_t* __restrict__ Wp_l,
        const float* __restrict__ bq, const float* __restrict__ bk_,
        const float* __restrict__ bv, int hop){
    extern __shared__ uint32_t smem_u[];
    uint32_t* sAh = smem_u;
    uint32_t* sAl = sAh + 7680;
    uint32_t* sBh = sAl + 7680;
    uint32_t* sBl = sBh + 6528;
    int room = g_idx[hop];
    int z = blockIdx.z;
    const float* bias = (z==0 ? bq : (z==1 ? bk_ : bv)) + (size_t)room*DD;
    const uint32_t* Wh = Wp_h + (size_t)z*SZP;
    const uint32_t* Wl = Wp_l + (size_t)z*SZP;
    int tid = threadIdx.x;
    int bm = blockIdx.y, bn = blockIdx.x;
    int warp = tid>>5, lane = tid&31;
    int g = lane>>2, t = lane&3;
    int wm = warp>>1, wn = warp&1;

    float acc[2][8][4] = {};
    gemm_core(Ah, Al, Wh, Wl, DD, DD, bm, bn, sAh, sAl, sBh, sBl, acc, tid, wm, wn, g, t);

    uint32_t* Ch = (z==0) ? g_qh : g_kh;
    uint32_t* Cl = (z==0) ? g_ql : g_kl;
    #pragma unroll
    for(int mt = 0; mt < 2; mt++){
        int row = bm*128 + wm*32 + mt*16 + g;
        #pragma unroll
        for(int nt = 0; nt < 8; nt++){
            int col = bn*128 + wn*64 + nt*8 + 2*t;
            float2 bi = *(const float2*)&bias[col];
            float v0 = acc[mt][nt][0] + bi.x;
            float v1 = acc[mt][nt][1] + bi.y;
            float v2 = acc[mt][nt][2] + bi.x;
            float v3 = acc[mt][nt][3] + bi.y;
            size_t i0 = (size_t)row*DD + col, i1 = (size_t)(row+8)*DD + col;
            if(z == 2){
                *(float2*)&g_v[i0] = make_float2(v0, v1);
                *(float2*)&g_v[i1] = make_float2(v2, v3);
            } else {
                uint32_t hh, ll;
                size_t w0 = (size_t)row*512 + (col>>1);
                size_t w1 = (size_t)(row+8)*512 + (col>>1);
                split2(v0, v1, hh, ll); Ch[w0] = hh; Cl[w0] = ll;
                split2(v2, v3, hh, ll); Ch[w1] = hh; Cl[w1] = ll;
            }
        }
    }
}

// ---------------- fused flash attention (bf16x3, online softmax) ----------------
__global__ void __launch_bounds__(128) k_flash(const float* __restrict__ v){
    int ti = 15 - (int)blockIdx.x;          // longest tiles first
    int bh = blockIdx.y; int b = bh>>4, h = bh&15;
    __shared__ uint32_t Qh[64][36], Ql[64][36];
    __shared__ uint32_t Kh[64][36], Kl[64][36];
    __shared__ uint32_t Vh[32][72], Vl[32][72];
    __shared__ float smax[2][64];
    __shared__ float sO[2][32][68];
    int tid = threadIdx.x;
    int warp = tid>>5, lane = tid&31;
    int g = lane>>2, t = lane&3;
    int wm = warp>>1, wn = warp&1;
    int vk2 = tid>>4, vn4 = tid&15;

    // load Q tile once
    #pragma unroll
    for(int i = 0; i < 4; i++){
        int idx = tid + 128*i;
        int r = idx>>3, c = (idx&7)*4;
        size_t qoff = ((size_t)(b*TT + ti*64 + r))*512 + h*32 + c;
        *(uint4*)&Qh[r][c] = *(const uint4*)(g_qh + qoff);
        *(uint4*)&Ql[r][c] = *(const uint4*)(g_ql + qoff);
    }

    float mo[4], l[4], O[2][8][4];
    #pragma unroll
    for(int i = 0; i < 4; i++){ mo[i] = -1e30f; l[i] = 0.f; }
    #pragma unroll
    for(int a = 0; a < 2; a++)
        #pragma unroll
        for(int n2 = 0; n2 < 8; n2++)
            #pragma unroll
            for(int j = 0; j < 4; j++) O[a][n2][j] = 0.f;

    for(int kt = 0; kt <= ti; kt++){
        __syncthreads();     // protect K/V/smax from previous iteration reads
        #pragma unroll
        for(int i = 0; i < 4; i++){
            int idx = tid + 128*i;
            int r = idx>>3, c = (idx&7)*4;
            size_t koff = ((size_t)(b*TT + kt*64 + r))*512 + h*32 + c;
            *(uint4*)&Kh[r][c] = *(const uint4*)(g_kh + koff);
            *(uint4*)&Kl[r][c] = *(const uint4*)(g_kl + koff);
        }
        #pragma unroll
        for(int i = 0; i < 4; i++){
            int k2 = vk2 + 8*i;
            const float* v0p = v + (size_t)(b*TT + kt*64 + 2*k2  )*DD + h*64 + vn4*4;
            const float* v1p = v + (size_t)(b*TT + kt*64 + 2*k2+1)*DD + h*64 + vn4*4;
            float4 a4 = *(const float4*)v0p;
            float4 b4 = *(const float4*)v1p;
            const float* r0 = (const float*)&a4;
            const float* r1 = (const float*)&b4;
            uint32_t hh[4], ll[4];
            #pragma unroll
            for(int j = 0; j < 4; j++) split2(r0[j], r1[j], hh[j], ll[j]);
            *(uint4*)&Vh[k2][vn4*4] = make_uint4(hh[0],hh[1],hh[2],hh[3]);
            *(uint4*)&Vl[k2][vn4*4] = make_uint4(ll[0],ll[1],ll[2],ll[3]);
        }
        __syncthreads();

        // S = Q K^T (bf16x3)
        float S[2][4][4];
        #pragma unroll
        for(int a = 0; a < 2; a++)
            #pragma unroll
            for(int n = 0; n < 4; n++)
                #pragma unroll
                for(int c = 0; c < 4; c++) S[a][n][c] = 0.f;
        #pragma unroll
        for(int kk2 = 0; kk2 < 32; kk2 += 8){
            uint32_t ah[2][4], al[2][4];
            #pragma unroll
            for(int mt = 0; mt < 2; mt++){
                int m0 = wm*32 + mt*16;
                ah[mt][0] = Qh[m0+g  ][kk2+t  ]; al[mt][0] = Ql[m0+g  ][kk2+t  ];
                ah[mt][1] = Qh[m0+g+8][kk2+t  ]; al[mt][1] = Ql[m0+g+8][kk2+t  ];
                ah[mt][2] = Qh[m0+g  ][kk2+t+4]; al[mt][2] = Ql[m0+g  ][kk2+t+4];
                ah[mt][3] = Qh[m0+g+8][kk2+t+4]; al[mt][3] = Ql[m0+g+8][kk2+t+4];
            }
            #pragma unroll
            for(int nt = 0; nt < 4; nt++){
                int n0 = wn*32 + nt*8 + g;
                uint32_t bh0 = Kh[n0][kk2+t  ], bl0 = Kl[n0][kk2+t  ];
                uint32_t bh1 = Kh[n0][kk2+t+4], bl1 = Kl[n0][kk2+t+4];
                #pragma unroll
                for(int mt = 0; mt < 2; mt++){
                    MMA3(S[mt][nt], ah[mt], al[mt], bh0, bh1, bl0, bl1);
                }
            }
        }
        // scale, causal mask (diag tile only), row max
        float rmax[4] = {-1e30f,-1e30f,-1e30f,-1e30f};
        #pragma unroll
        for(int mt = 0; mt < 2; mt++)
        #pragma unroll
        for(int nt = 0; nt < 4; nt++)
        #pragma unroll
        for(int j = 0; j < 4; j++){
            float val = S[mt][nt][j]*0.125f;
            if(kt == ti){
                int row = wm*32 + mt*16 + g + ((j>>1)<<3);
                int col = wn*32 + nt*8 + 2*t + (j&1);
                if(col > row) val = -1e30f;
            }
            S[mt][nt][j] = val;
            int ri = mt*2 + (j>>1);
            rmax[ri] = fmaxf(rmax[ri], val);
        }
        #pragma unroll
        for(int i = 0; i < 4; i++){
            rmax[i] = fmaxf(rmax[i], __shfl_xor_sync(0xffffffffu, rmax[i], 1));
            rmax[i] = fmaxf(rmax[i], __shfl_xor_sync(0xffffffffu, rmax[i], 2));
        }
        if(t == 0){
            #pragma unroll
            for(int mt = 0; mt < 2; mt++){
                smax[wn][wm*32 + mt*16 + g    ] = rmax[mt*2];
                smax[wn][wm*32 + mt*16 + g + 8] = rmax[mt*2+1];
            }
        }
        __syncthreads();
        float mn[4], alp[4];
        #pragma unroll
        for(int mt = 0; mt < 2; mt++)
        #pragma unroll
        for(int rr = 0; rr < 2; rr++){
            int row = wm*32 + mt*16 + g + rr*8;
            float mm = fmaxf(smax[0][row], smax[1][row]);
            int i = mt*2 + rr;
            mn[i] = fmaxf(mo[i], mm);
            alp[i] = expf(mo[i] - mn[i]);
            mo[i] = mn[i];
        }
        // P = exp(S - mn); partial rowsum
        float rs[4] = {0.f,0.f,0.f,0.f};
        #pragma unroll
        for(int mt = 0; mt < 2; mt++)
        #pragma unroll
        for(int nt = 0; nt < 4; nt++)
        #pragma unroll
        for(int j = 0; j < 4; j++){
            int i = mt*2 + (j>>1);
            float e = expf(S[mt][nt][j] - mn[i]);
            S[mt][nt][j] = e;
            rs[i] += e;
        }
        #pragma unroll
        for(int i = 0; i < 4; i++){
            rs[i] += __shfl_xor_sync(0xffffffffu, rs[i], 1);
            rs[i] += __shfl_xor_sync(0xffffffffu, rs[i], 2);
            l[i] = l[i]*alp[i] + rs[i];
        }
        // rescale O
        #pragma unroll
        for(int mt = 0; mt < 2; mt++)
        #pragma unroll
        for(int n2 = 0; n2 < 8; n2++)
        #pragma unroll
        for(int j = 0; j < 4; j++)
            O[mt][n2][j] *= alp[mt*2 + (j>>1)];
        // O += P @ V
        #pragma unroll
        for(int kg = 0; kg < 2; kg++){
            uint32_t ah[2][4], al[2][4];
            #pragma unroll
            for(int mt = 0; mt < 2; mt++){
                split2(S[mt][kg*2  ][0], S[mt][kg*2  ][1], ah[mt][0], al[mt][0]);
                split2(S[mt][kg*2  ][2], S[mt][kg*2  ][3], ah[mt][1], al[mt][1]);
                split2(S[mt][kg*2+1][0], S[mt][kg*2+1][1], ah[mt][2], al[mt][2]);
                split2(S[mt][kg*2+1][2], S[mt][kg*2+1][3], ah[mt][3], al[mt][3]);
            }
            int k2b = wn*16 + kg*8;
            #pragma unroll
            for(int n2 = 0; n2 < 8; n2++){
                int n0 = n2*8 + g;
                uint32_t bh0 = Vh[k2b+t  ][n0], bl0 = Vl[k2b+t  ][n0];
                uint32_t bh1 = Vh[k2b+t+4][n0], bl1 = Vl[k2b+t+4][n0];
                #pragma unroll
                for(int mt = 0; mt < 2; mt++){
                    MMA3(O[mt][n2], ah[mt], al[mt], bh0, bh1, bl0, bl1);
                }
            }
        }
    }
    // combine key halves across wn, normalize, write split o planes
    __syncthreads();
    if(wn == 1){
        #pragma unroll
        for(int mt = 0; mt < 2; mt++)
        #pragma unroll
        for(int n2 = 0; n2 < 8; n2++)
        #pragma unroll
        for(int j = 0; j < 4; j++)
            sO[wm][lane][mt*32 + n2*4 + j] = O[mt][n2][j];
        #pragma unroll
        for(int i = 0; i < 4; i++) sO[wm][lane][64+i] = l[i];
    }
    __syncthreads();
    if(wn == 0){
        float inv[4];
        #pragma unroll
        for(int i = 0; i < 4; i++) inv[i] = 1.0f/(l[i] + sO[wm][lane][64+i]);
        #pragma unroll
        for(int mt = 0; mt < 2; mt++){
            int row0 = ti*64 + wm*32 + mt*16 + g;
            #pragma unroll
            for(int n2 = 0; n2 < 8; n2++){
                float o0 = (O[mt][n2][0] + sO[wm][lane][mt*32 + n2*4 + 0])*inv[mt*2];
                float o1 = (O[mt][n2][1] + sO[wm][lane][mt*32 + n2*4 + 1])*inv[mt*2];
                float o2 = (O[mt][n2][2] + sO[wm][lane][mt*32 + n2*4 + 2])*inv[mt*2+1];
                float o3 = (O[mt][n2][3] + sO[wm][lane][mt*32 + n2*4 + 3])*inv[mt*2+1];
                int col = n2*8 + 2*t;
                size_t w0 = ((size_t)(b*TT + row0))*512 + (h*64 + col)/2;
                size_t w1 = ((size_t)(b*TT + row0 + 8))*512 + (h*64 + col)/2;
                uint32_t hh, ll2;
                split2(o0, o1, hh, ll2); g_oh[w0] = hh; g_ol[w0] = ll2;
                split2(o2, o3, hh, ll2); g_oh[w1] = hh; g_ol[w1] = ll2;
            }
        }
    }
}

extern "C" void kernel_launch(void* const* d_in, const int* in_sizes, int n_in,
                              void* d_out, int out_size){
    const float* x         = (const float*)d_in[0];
    const float* summaries = (const float*)d_in[1];
    const float* ctx_w     = (const float*)d_in[2];
    const float* ctx_b     = (const float*)d_in[3];
    const float* base_adj  = (const float*)d_in[4];
    const float* warp_w    = (const float*)d_in[5];
    const float* warp_b    = (const float*)d_in[6];
    const float* gate_w    = (const float*)d_in[7];
    const float* gate_b    = (const float*)d_in[8];
    const float* g1_w      = (const float*)d_in[9];
    const float* g1_b      = (const float*)d_in[10];
    const float* g2_w      = (const float*)d_in[11];
    const float* g2_b      = (const float*)d_in[12];
    const float* ln1_g     = (const float*)d_in[13];
    const float* ln1_b     = (const float*)d_in[14];
    const float* wq        = (const float*)d_in[15];
    const float* bq        = (const float*)d_in[16];
    const float* wk        = (const float*)d_in[17];
    const float* bk        = (const float*)d_in[18];
    const float* wv        = (const float*)d_in[19];
    const float* bv        = (const float*)d_in[20];
    const float* wo        = (const float*)d_in[21];
    const float* bo        = (const float*)d_in[22];
    const float* ln2_g     = (const float*)d_in[23];
    const float* ln2_b     = (const float*)d_in[24];
    const float* ff1_w     = (const float*)d_in[25];
    const float* ff1_b     = (const float*)d_in[26];
    const float* ff2_w     = (const float*)d_in[27];
    const float* ff2_b     = (const float*)d_in[28];
    float* out = (float*)d_out;

    float *p_cur, *p_xo, *p_v, *p_gate;
    uint32_t *p_oh,*p_ol,*p_nh,*p_nl,*p_mh,*p_ml,*p_wph,*p_wpl;
    cudaGetSymbolAddress((void**)&p_cur,  g_cur);
    cudaGetSymbolAddress((void**)&p_xo,   g_xo);
    cudaGetSymbolAddress((void**)&p_v,    g_v);
    cudaGetSymbolAddress((void**)&p_gate, g_gate);
    cudaGetSymbolAddress((void**)&p_oh, g_oh);  cudaGetSymbolAddress((void**)&p_ol, g_ol);
    cudaGetSymbolAddress((void**)&p_nh, g_normh); cudaGetSymbolAddress((void**)&p_nl, g_norml);
    cudaGetSymbolAddress((void**)&p_mh, g_midh); cudaGetSymbolAddress((void**)&p_ml, g_midl);
    cudaGetSymbolAddress((void**)&p_wph, g_wph); cudaGetSymbolAddress((void**)&p_wpl, g_wpl);

    cudaFuncSetAttribute(k_gemm3, cudaFuncAttributeMaxDynamicSharedMemorySize, DSMEM_BYTES);
    cudaFuncSetAttribute(k_qkv,   cudaFuncAttributeMaxDynamicSharedMemorySize, DSMEM_BYTES);

    // ---- router ----
    k_meanT_part<<<dim3(BB,32),256>>>(x);
    k_meanT_reduce<<<BB,256>>>();
    k_ctx<<<dim3(BB,32),128>>>(ctx_w, ctx_b);
    k_route1<<<dim3(BB,80),128>>>(warp_w, summaries, gate_w);
    k_route2<<<1,32>>>(base_adj, warp_b, gate_b,
                       out + BTD, out + BTD + 32, out + BTD + 32 + 256);

    // ---- 3 hops ----
    for(int hop = 0; hop < 3; hop++){
        const float* cin = (hop == 0) ? x : p_cur;
        float* cout = (hop == 2) ? out : p_cur;

        k_packw<<<SZP/256,256>>>(wq,  p_wph+0*SZP, p_wpl+0*SZP, DD,  hop, (long)DD*DD);
        k_packw<<<SZP/256,256>>>(wk,  p_wph+1*SZP, p_wpl+1*SZP, DD,  hop, (long)DD*DD);
        k_packw<<<SZP/256,256>>>(wv,  p_wph+2*SZP, p_wpl+2*SZP, DD,  hop, (long)DD*DD);
        k_packw<<<SZP/256,256>>>(wo,  p_wph+3*SZP, p_wpl+3*SZP, DD,  hop, (long)DD*DD);
        k_packw<<<SZF/256,256>>>(ff1_w, p_wph+4*SZP,     p_wpl+4*SZP,     DFF, hop, (long)DD*DFF);
        k_packw<<<SZF/256,256>>>(ff2_w, p_wph+4*SZP+SZF, p_wpl+4*SZP+SZF, DD,  hop, (long)DFF*DD);

        if(hop > 0){
            k_meanT_part<<<dim3(BB,32),256>>>(cin);
            k_meanT_reduce<<<BB,256>>>();
        }
        k_g1<<<dim3(BB,16),256>>>(g1_w, g1_b, hop);
        k_g2<<<1,256>>>(g2_w, g2_b, hop);
        k_ln2<<<BT,256>>>(cin, ln1_g, ln1_b, hop, p_gate, p_nh, p_nl);
        k_qkv<<<dim3(8,32,3),256,DSMEM_BYTES>>>(p_nh, p_nl, p_wph, p_wpl, bq, bk, bv, hop);
        k_flash<<<dim3(16,BB*HH),128>>>(p_v);
        k_gemm3<<<dim3(8,32),256,DSMEM_BYTES>>>(p_oh,p_ol, p_wph+3*SZP,p_wpl+3*SZP, bo, DD, hop,
                                    cin, p_gate, nullptr, p_xo, nullptr,nullptr, DD, DD, 0, 0);
        k_ln2<<<BT,256>>>(p_xo, ln2_g, ln2_b, hop, nullptr, p_nh, p_nl);
        k_gemm3<<<dim3(32,32),256,DSMEM_BYTES>>>(p_nh,p_nl, p_wph+4*SZP,p_wpl+4*SZP, ff1_b, DFF, hop,
                                    nullptr,nullptr,nullptr, nullptr, p_mh,p_ml, DFF, DD, 1, 1);
        k_gemm3<<<dim3(8,32),256,DSMEM_BYTES>>>(p_mh,p_ml, p_wph+4*SZP+SZF,p_wpl+4*SZP+SZF, ff2_b, DD, hop,
                                    p_xo, nullptr, cin, cout, nullptr,nullptr, DD, DFF, 0, 2);
    }
}